// round 11
// baseline (speedup 1.0000x reference)
#include <cuda_runtime.h>
#include <cuda_bf16.h>
#include <math.h>
#include <stdint.h>

// ---------------- problem constants ----------------
#define BB   2      // batch
#define SL   4096   // token seq len
#define GG   128    // global tokens
#define DM   1024   // embed dim
#define NH   16     // heads
#define FF   64     // head dim
#define NBL  8      // local blocks per seq
#define KBL  512    // block size

typedef __nv_bfloat16 bf16;

// ---------------- scratch (static device, no allocation) ----------------
// split-bf16 operands
__device__ bf16 g_tokh[(size_t)BB*SL*DM],  g_tokl[(size_t)BB*SL*DM];
__device__ bf16 g_globh[(size_t)BB*GG*DM], g_globl[(size_t)BB*GG*DM];
__device__ bf16 g_wqh[(size_t)DM*DM], g_wql[(size_t)DM*DM];
__device__ bf16 g_wkh[(size_t)DM*DM], g_wkl[(size_t)DM*DM];
__device__ bf16 g_wvh[(size_t)DM*DM], g_wvl[(size_t)DM*DM];
__device__ bf16 g_woh[(size_t)DM*DM], g_wol[(size_t)DM*DM];
__device__ bf16 g_aLh[(size_t)BB*SL*DM],  g_aLl[(size_t)BB*SL*DM];
__device__ bf16 g_aGh[(size_t)BB*GG*DM],  g_aGl[(size_t)BB*GG*DM];

// head-split projections [B,H,L,F], bf16 hi/lo
__device__ bf16 g_qTh[(size_t)BB*NH*SL*FF], g_qTl[(size_t)BB*NH*SL*FF];
__device__ bf16 g_kTh[(size_t)BB*NH*SL*FF], g_kTl[(size_t)BB*NH*SL*FF];
__device__ bf16 g_vTh[(size_t)BB*NH*SL*FF], g_vTl[(size_t)BB*NH*SL*FF];
__device__ bf16 g_qGh[(size_t)BB*NH*GG*FF], g_qGl[(size_t)BB*NH*GG*FF];
__device__ bf16 g_kGh[(size_t)BB*NH*GG*FF], g_kGl[(size_t)BB*NH*GG*FF];
__device__ bf16 g_vGh[(size_t)BB*NH*GG*FF], g_vGl[(size_t)BB*NH*GG*FF];

// ---------------- helpers (base-target ISA only) ----------------
__device__ __forceinline__ uint32_t smem_to_u32(const void* p) {
    uint32_t a;
    asm("{ .reg .u64 t; cvta.to.shared.u64 t, %1; cvt.u32.u64 %0, t; }" : "=r"(a) : "l"(p));
    return a;
}
#define CP_ASYNC16(saddr, gptr) \
    asm volatile("cp.async.cg.shared.global [%0], [%1], 16;" :: "r"(saddr), "l"(gptr))
#define CP_COMMIT() asm volatile("cp.async.commit_group;" ::: "memory")
#define CP_WAIT1()  asm volatile("cp.async.wait_group 1;" ::: "memory")
#define CP_WAIT0()  asm volatile("cp.async.wait_group 0;" ::: "memory")

#define LDMX4(d0, d1, d2, d3, addr) \
    asm volatile("ldmatrix.sync.aligned.m8n8.x4.shared.b16 {%0,%1,%2,%3}, [%4];" \
        : "=r"(d0), "=r"(d1), "=r"(d2), "=r"(d3) : "r"(addr))
#define LDMT4(d0, d1, d2, d3, addr) \
    asm volatile("ldmatrix.sync.aligned.m8n8.x4.trans.shared.b16 {%0,%1,%2,%3}, [%4];" \
        : "=r"(d0), "=r"(d1), "=r"(d2), "=r"(d3) : "r"(addr))

#define MMA_BF16(c, a, b) \
    asm volatile("mma.sync.aligned.m16n8k16.row.col.f32.bf16.bf16.f32 " \
        "{%0,%1,%2,%3}, {%4,%5,%6,%7}, {%8,%9}, {%0,%1,%2,%3};" \
        : "+f"((c)[0]), "+f"((c)[1]), "+f"((c)[2]), "+f"((c)[3]) \
        : "r"((a)[0]), "r"((a)[1]), "r"((a)[2]), "r"((a)[3]), \
          "r"((b)[0]), "r"((b)[1]))

__device__ __forceinline__ uint32_t pack_bf16x2(float x, float y) {
    __nv_bfloat162 t = __floats2bfloat162_rn(x, y);
    return *reinterpret_cast<uint32_t*>(&t);
}

// ---------------- fused split fp32 -> bf16 hi/lo (all inputs, one launch) ----------------
struct SplitJob { const float* x; bf16* hi; bf16* lo; int n4; };
struct SplitJobs { SplitJob j[6]; };

__global__ __launch_bounds__(256) void split_all_kernel(SplitJobs jobs)
{
    SplitJob jb = jobs.j[blockIdx.y];
    int i = blockIdx.x * 256 + threadIdx.x;
    if (i >= jb.n4) return;
    float4 v = ((const float4*)jb.x)[i];
    __nv_bfloat162 h0 = __floats2bfloat162_rn(v.x, v.y);
    __nv_bfloat162 h1 = __floats2bfloat162_rn(v.z, v.w);
    float rx = v.x - __bfloat162float(__low2bfloat16(h0));
    float ry = v.y - __bfloat162float(__high2bfloat16(h0));
    float rz = v.z - __bfloat162float(__low2bfloat16(h1));
    float rw = v.w - __bfloat162float(__high2bfloat16(h1));
    ((__nv_bfloat162*)jb.hi)[2*i]   = h0;
    ((__nv_bfloat162*)jb.hi)[2*i+1] = h1;
    ((__nv_bfloat162*)jb.lo)[2*i]   = __floats2bfloat162_rn(rx, ry);
    ((__nv_bfloat162*)jb.lo)[2*i+1] = __floats2bfloat162_rn(rz, rw);
}

// ---------------- mma.sync split-bf16 GEMM ----------------
// 512 threads, 16 warps (4M x 4N), warp tile 32x32; 128x128 CTA tile; BK=32.
// 2-stage cp.async pipeline (80KB smem). C = Ah*Wh + Ah*Wl + Al*Wh.
struct GemmOp {
    const bf16 *Wh, *Wl;
    bf16 *Ch, *Cl;
    float* Cf;
    float scale;
};

#define ROWB    80
#define TILEB   (128 * ROWB)
#define STAGEB  (4 * TILEB)
#define SMEMB   (2 * STAGEB)     // 81920

__global__ __launch_bounds__(512, 1) void gemm_hmma(
    const bf16* __restrict__ Ah, const bf16* __restrict__ Al,
    GemmOp op0, GemmOp op1, GemmOp op2, int Lhead)
{
    extern __shared__ __align__(128) char smem[];
    const uint32_t sbase = smem_to_u32(smem);
    const int tid  = threadIdx.x;
    const int wid  = tid >> 5;
    const int lane = tid & 31;
    const int warpM = wid & 3, warpN = wid >> 2;   // 4 x 4 warps
    const int m0 = blockIdx.y * 128;
    const int e0 = blockIdx.x * 128;

    GemmOp op = (blockIdx.z == 0) ? op0 : ((blockIdx.z == 1) ? op1 : op2);

    const bf16* srcs[4] = {
        Ah + (size_t)m0 * DM, Al + (size_t)m0 * DM,
        op.Wh + (size_t)e0 * DM, op.Wl + (size_t)e0 * DM };

    float acc[2][4][4];
    #pragma unroll
    for (int i = 0; i < 2; i++)
        #pragma unroll
        for (int j = 0; j < 4; j++)
            #pragma unroll
            for (int k = 0; k < 4; k++) acc[i][j][k] = 0.f;

    // 2048 16B-chunks per stage / 512 threads = 4 per thread
    auto issue = [&](int stg, int k0) {
        uint32_t sb = sbase + stg * STAGEB;
        #pragma unroll
        for (int i = 0; i < 4; i++) {
            int c = tid + i * 512;
            int t = c >> 9, u = c & 511;
            int row = u >> 2, seg = u & 3;
            const bf16* g = srcs[t] + (size_t)row * DM + k0 + seg * 8;
            CP_ASYNC16(sb + t * TILEB + row * ROWB + seg * 16, g);
        }
    };

    issue(0, 0);
    CP_COMMIT();

    #pragma unroll 1
    for (int it = 0; it < 32; it++) {
        if (it + 1 < 32) {
            issue((it + 1) & 1, (it + 1) * 32);
            CP_COMMIT();
            CP_WAIT1();
        } else {
            CP_WAIT0();
        }
        __syncthreads();

        const uint32_t sb  = sbase + (it & 1) * STAGEB;
        const uint32_t sAh = sb;
        const uint32_t sAl = sb + TILEB;
        const uint32_t sBh = sb + 2 * TILEB;
        const uint32_t sBl = sb + 3 * TILEB;

        #pragma unroll
        for (int ks = 0; ks < 2; ks++) {
            uint32_t ah[2][4], al[2][4];
            {
                int r = lane & 15, c8 = lane >> 4;
                #pragma unroll
                for (int mf = 0; mf < 2; mf++) {
                    uint32_t off = (uint32_t)(warpM * 32 + mf * 16 + r) * ROWB
                                 + (uint32_t)(ks * 16 + c8 * 8) * 2;
                    LDMX4(ah[mf][0], ah[mf][1], ah[mf][2], ah[mf][3], sAh + off);
                    LDMX4(al[mf][0], al[mf][1], al[mf][2], al[mf][3], sAl + off);
                }
            }
            uint32_t bh[4][2], bl[4][2];
            {
                int rr = lane & 7, sub = lane >> 3;
                #pragma unroll
                for (int nf2 = 0; nf2 < 2; nf2++) {
                    int n  = warpN * 32 + nf2 * 16 + ((sub >> 1) << 3) + rr;
                    int kk = ks * 16 + ((sub & 1) << 3);
                    uint32_t off = (uint32_t)n * ROWB + (uint32_t)kk * 2;
                    LDMX4(bh[2*nf2][0], bh[2*nf2][1], bh[2*nf2+1][0], bh[2*nf2+1][1], sBh + off);
                    LDMX4(bl[2*nf2][0], bl[2*nf2][1], bl[2*nf2+1][0], bl[2*nf2+1][1], sBl + off);
                }
            }
            #pragma unroll
            for (int mf = 0; mf < 2; mf++)
                #pragma unroll
                for (int nf = 0; nf < 4; nf++) {
                    MMA_BF16(acc[mf][nf], ah[mf], bh[nf]);
                    MMA_BF16(acc[mf][nf], ah[mf], bl[nf]);
                    MMA_BF16(acc[mf][nf], al[mf], bh[nf]);
                }
        }
        __syncthreads();
    }

    #pragma unroll
    for (int mf = 0; mf < 2; mf++) {
        #pragma unroll
        for (int nf = 0; nf < 4; nf++) {
            int rbase = m0 + warpM * 32 + mf * 16 + (lane >> 2);
            int e = e0 + warpN * 32 + nf * 8 + (lane & 3) * 2;
            #pragma unroll
            for (int half = 0; half < 2; half++) {
                int m = rbase + half * 8;
                float vx = acc[mf][nf][half * 2 + 0] * op.scale;
                float vy = acc[mf][nf][half * 2 + 1] * op.scale;
                if (Lhead > 0) {
                    int bI = m / Lhead, l = m - bI * Lhead;
                    size_t idx = ((((size_t)bI * NH + (e >> 6)) * (size_t)Lhead + l) << 6) + (e & 63);
                    __nv_bfloat162 hi = __floats2bfloat162_rn(vx, vy);
                    float lx = vx - __bfloat162float(__low2bfloat16(hi));
                    float ly = vy - __bfloat162float(__high2bfloat16(hi));
                    *(__nv_bfloat162*)&op.Ch[idx] = hi;
                    *(__nv_bfloat162*)&op.Cl[idx] = __floats2bfloat162_rn(lx, ly);
                } else {
                    float2 v; v.x = vx; v.y = vy;
                    *(float2*)&op.Cf[(size_t)m * DM + e] = v;
                }
            }
        }
    }
}

// ---------------- flash attention (HMMA, split-bf16 in AND out) ----------------
#define QROW     144
#define AQH_OFF  0
#define AQL_OFF  18432
#define AKV_OFF  36864
#define AKV_ARR  9216
#define AKV_BUF  36864
#define AMSK_OFF 110592
#define ASMEM    111104

__global__ __launch_bounds__(256, 1) void fattn(
    const bf16* __restrict__ Qh, const bf16* __restrict__ Ql,
    const bf16* __restrict__ KGh, const bf16* __restrict__ KGl,
    const bf16* __restrict__ VGh, const bf16* __restrict__ VGl,
    const bf16* __restrict__ KTh, const bf16* __restrict__ KTl,
    const bf16* __restrict__ VTh, const bf16* __restrict__ VTl,
    const float* __restrict__ mask,
    bf16* __restrict__ outh, bf16* __restrict__ outl,
    int NB, int QL, int X)
{
    extern __shared__ __align__(128) char smem[];
    const uint32_t sbase = smem_to_u32(smem);
    const int tid  = threadIdx.x;
    const int wid  = tid >> 5;
    const int lane = tid & 31;
    const int bh = blockIdx.x / NB;
    const int n  = blockIdx.x - bh * NB;
    const int b  = bh >> 4, h = bh & 15;
    const int LTOT = NB * QL;
    const int LO   = n * QL;
    const int q0   = n * QL + blockIdx.y * 128;
    const int T    = X >> 6;

    const bf16* gk[4] = { KGh, KGl, VGh, VGl };
    const bf16* tk[4] = { KTh, KTl, VTh, VTl };

    auto issueKV = [&](int stg, int tile) {
        int xb = tile * 64;
        uint32_t sb = sbase + AKV_OFF + stg * AKV_BUF;
        #pragma unroll
        for (int i = 0; i < 8; i++) {
            int c = tid + i * 256;
            int arr = c >> 9, u = c & 511;
            int row = u >> 3, seg = u & 7;
            int x = xb + row;
            const bf16* src = (x < GG)
                ? gk[arr] + (((size_t)bh * GG + x) << 6) + seg * 8
                : tk[arr] + (((size_t)bh * SL + (x - GG + LO)) << 6) + seg * 8;
            CP_ASYNC16(sb + arr * AKV_ARR + row * QROW + seg * 16, src);
        }
        if (tid < 64) {
            int x = xb + tid;
            float mv = (x < GG) ? 0.f : mask[(size_t)b * SL + x - GG + LO];
            *(float*)(smem + AMSK_OFF + stg * 256 + tid * 4) = mv;
        }
    };

    #pragma unroll
    for (int i = 0; i < 8; i++) {
        int c = tid + i * 256;
        int arr = c >> 10, u = c & 1023;
        int row = u >> 3, seg = u & 7;
        const bf16* src = (arr ? Ql : Qh) + (((size_t)bh * LTOT + q0 + row) << 6) + seg * 8;
        CP_ASYNC16(sbase + (arr ? AQL_OFF : AQH_OFF) + row * QROW + seg * 16, src);
    }
    issueKV(0, 0);
    CP_COMMIT();

    float o[8][4];
    #pragma unroll
    for (int i = 0; i < 8; i++)
        #pragma unroll
        for (int j = 0; j < 4; j++) o[i][j] = 0.f;
    float runA = -INFINITY, runB = -INFINITY, lA = 0.f, lB = 0.f;

    const int r = lane & 15, c8 = lane >> 4;
    const int rr = lane & 7, sub = lane >> 3;

    #pragma unroll 1
    for (int t = 0; t < T; t++) {
        if (t + 1 < T) {
            issueKV((t + 1) & 1, t + 1);
            CP_COMMIT();
            CP_WAIT1();
        } else {
            CP_WAIT0();
        }
        __syncthreads();

        const uint32_t kvb = sbase + AKV_OFF + (t & 1) * AKV_BUF;
        const uint32_t sKh = kvb, sKl = kvb + AKV_ARR;
        const uint32_t sVh = kvb + 2 * AKV_ARR, sVl = kvb + 3 * AKV_ARR;
        const char* msk = smem + AMSK_OFF + (t & 1) * 256;

        float s[8][4];
        #pragma unroll
        for (int i = 0; i < 8; i++)
            #pragma unroll
            for (int j = 0; j < 4; j++) s[i][j] = 0.f;

        #pragma unroll
        for (int ks = 0; ks < 4; ks++) {
            uint32_t qh4[4], ql4[4];
            uint32_t qoff = (uint32_t)(wid * 16 + r) * QROW + (uint32_t)(ks * 16 + c8 * 8) * 2;
            LDMX4(qh4[0], qh4[1], qh4[2], qh4[3], sbase + AQH_OFF + qoff);
            LDMX4(ql4[0], ql4[1], ql4[2], ql4[3], sbase + AQL_OFF + qoff);
            uint32_t kh8[8][2], kl8[8][2];
            #pragma unroll
            for (int nf2 = 0; nf2 < 4; nf2++) {
                uint32_t boff = (uint32_t)(nf2 * 16 + ((sub >> 1) << 3) + rr) * QROW
                              + (uint32_t)(ks * 16 + ((sub & 1) << 3)) * 2;
                LDMX4(kh8[2*nf2][0], kh8[2*nf2][1], kh8[2*nf2+1][0], kh8[2*nf2+1][1], sKh + boff);
                LDMX4(kl8[2*nf2][0], kl8[2*nf2][1], kl8[2*nf2+1][0], kl8[2*nf2+1][1], sKl + boff);
            }
            #pragma unroll
            for (int nf = 0; nf < 8; nf++) {
                MMA_BF16(s[nf], qh4, kh8[nf]);
                MMA_BF16(s[nf], qh4, kl8[nf]);
                MMA_BF16(s[nf], ql4, kh8[nf]);
            }
        }

        #pragma unroll
        for (int nf = 0; nf < 8; nf++) {
            float2 mv = *(const float2*)(msk + (nf * 8 + (lane & 3) * 2) * 4);
            s[nf][0] += mv.x; s[nf][1] += mv.y;
            s[nf][2] += mv.x; s[nf][3] += mv.y;
        }
        float mA = -INFINITY, mB = -INFINITY;
        #pragma unroll
        for (int nf = 0; nf < 8; nf++) {
            mA = fmaxf(mA, fmaxf(s[nf][0], s[nf][1]));
            mB = fmaxf(mB, fmaxf(s[nf][2], s[nf][3]));
        }
        mA = fmaxf(mA, __shfl_xor_sync(0xffffffffu, mA, 1));
        mA = fmaxf(mA, __shfl_xor_sync(0xffffffffu, mA, 2));
        mB = fmaxf(mB, __shfl_xor_sync(0xffffffffu, mB, 1));
        mB = fmaxf(mB, __shfl_xor_sync(0xffffffffu, mB, 2));
        float nA = fmaxf(runA, mA), nB = fmaxf(runB, mB);
        float cA = __expf(runA - nA), cB = __expf(runB - nB);
        runA = nA; runB = nB;

        uint32_t phA[8], phB[8], plA[8], plB[8];
        float sumA = 0.f, sumB = 0.f;
        #pragma unroll
        for (int nf = 0; nf < 8; nf++) {
            float p0 = __expf(s[nf][0] - nA), p1 = __expf(s[nf][1] - nA);
            float p2 = __expf(s[nf][2] - nB), p3 = __expf(s[nf][3] - nB);
            sumA += p0 + p1; sumB += p2 + p3;
            __nv_bfloat162 h01 = __floats2bfloat162_rn(p0, p1);
            __nv_bfloat162 h23 = __floats2bfloat162_rn(p2, p3);
            phA[nf] = *reinterpret_cast<uint32_t*>(&h01);
            phB[nf] = *reinterpret_cast<uint32_t*>(&h23);
            plA[nf] = pack_bf16x2(p0 - __bfloat162float(__low2bfloat16(h01)),
                                  p1 - __bfloat162float(__high2bfloat16(h01)));
            plB[nf] = pack_bf16x2(p2 - __bfloat162float(__low2bfloat16(h23)),
                                  p3 - __bfloat162float(__high2bfloat16(h23)));
        }
        sumA += __shfl_xor_sync(0xffffffffu, sumA, 1);
        sumA += __shfl_xor_sync(0xffffffffu, sumA, 2);
        sumB += __shfl_xor_sync(0xffffffffu, sumB, 1);
        sumB += __shfl_xor_sync(0xffffffffu, sumB, 2);
        lA = lA * cA + sumA;
        lB = lB * cB + sumB;
        #pragma unroll
        for (int i = 0; i < 8; i++) {
            o[i][0] *= cA; o[i][1] *= cA; o[i][2] *= cB; o[i][3] *= cB;
        }

        #pragma unroll
        for (int ks = 0; ks < 4; ks++) {
            uint32_t aH[4] = { phA[2*ks], phB[2*ks], phA[2*ks+1], phB[2*ks+1] };
            uint32_t aL4[4] = { plA[2*ks], plB[2*ks], plA[2*ks+1], plB[2*ks+1] };
            #pragma unroll
            for (int jf2 = 0; jf2 < 4; jf2++) {
                uint32_t voff = (uint32_t)(ks * 16 + r) * QROW + (uint32_t)(jf2 * 16 + c8 * 8) * 2;
                uint32_t vh4[4], vl4[4];
                LDMT4(vh4[0], vh4[1], vh4[2], vh4[3], sVh + voff);
                LDMT4(vl4[0], vl4[1], vl4[2], vl4[3], sVl + voff);
                uint32_t b0h[2] = { vh4[0], vh4[1] }, b1h[2] = { vh4[2], vh4[3] };
                uint32_t b0l[2] = { vl4[0], vl4[1] }, b1l[2] = { vl4[2], vl4[3] };
                MMA_BF16(o[2*jf2],   aH,  b0h);
                MMA_BF16(o[2*jf2],   aH,  b0l);
                MMA_BF16(o[2*jf2],   aL4, b0h);
                MMA_BF16(o[2*jf2+1], aH,  b1h);
                MMA_BF16(o[2*jf2+1], aH,  b1l);
                MMA_BF16(o[2*jf2+1], aL4, b1h);
            }
        }
        __syncthreads();
    }

    float iA = 1.f / lA, iB = 1.f / lB;
    int rowA = q0 + wid * 16 + (lane >> 2);
    size_t baseA = ((size_t)b * LTOT + rowA) * DM + h * 64;
    size_t baseB = baseA + (size_t)8 * DM;
    #pragma unroll
    for (int nf = 0; nf < 8; nf++) {
        int f = nf * 8 + (lane & 3) * 2;
        float ax = o[nf][0] * iA, ay = o[nf][1] * iA;
        float bx = o[nf][2] * iB, by = o[nf][3] * iB;
        __nv_bfloat162 hA = __floats2bfloat162_rn(ax, ay);
        __nv_bfloat162 hB = __floats2bfloat162_rn(bx, by);
        *(__nv_bfloat162*)&outh[baseA + f] = hA;
        *(__nv_bfloat162*)&outh[baseB + f] = hB;
        *(__nv_bfloat162*)&outl[baseA + f] =
            __floats2bfloat162_rn(ax - __bfloat162float(__low2bfloat16(hA)),
                                  ay - __bfloat162float(__high2bfloat16(hA)));
        *(__nv_bfloat162*)&outl[baseB + f] =
            __floats2bfloat162_rn(bx - __bfloat162float(__low2bfloat16(hB)),
                                  by - __bfloat162float(__high2bfloat16(hB)));
    }
}

// ---------------- host ----------------
extern "C" void kernel_launch(void* const* d_in, const int* in_sizes, int n_in,
                              void* d_out, int out_size)
{
    const float* tok  = (const float*)d_in[0];
    const float* glob = (const float*)d_in[1];
    const float* mask = (const float*)d_in[2];
    const float* Wq   = (const float*)d_in[3];
    const float* Wk   = (const float*)d_in[4];
    const float* Wv   = (const float*)d_in[5];
    const float* Wo   = (const float*)d_in[6];
    float* out = (float*)d_out;

    bf16 *tokh,*tokl,*globh,*globl,*wqh,*wql,*wkh,*wkl,*wvh,*wvl,*woh,*wol,*aLh,*aLl,*aGh,*aGl;
    cudaGetSymbolAddress((void**)&tokh, g_tokh);   cudaGetSymbolAddress((void**)&tokl, g_tokl);
    cudaGetSymbolAddress((void**)&globh, g_globh); cudaGetSymbolAddress((void**)&globl, g_globl);
    cudaGetSymbolAddress((void**)&wqh, g_wqh);     cudaGetSymbolAddress((void**)&wql, g_wql);
    cudaGetSymbolAddress((void**)&wkh, g_wkh);     cudaGetSymbolAddress((void**)&wkl, g_wkl);
    cudaGetSymbolAddress((void**)&wvh, g_wvh);     cudaGetSymbolAddress((void**)&wvl, g_wvl);
    cudaGetSymbolAddress((void**)&woh, g_woh);     cudaGetSymbolAddress((void**)&wol, g_wol);
    cudaGetSymbolAddress((void**)&aLh, g_aLh);     cudaGetSymbolAddress((void**)&aLl, g_aLl);
    cudaGetSymbolAddress((void**)&aGh, g_aGh);     cudaGetSymbolAddress((void**)&aGl, g_aGl);

    bf16 *qTh,*qTl,*kTh,*kTl,*vTh,*vTl,*qGh,*qGl,*kGh,*kGl,*vGh,*vGl;
    cudaGetSymbolAddress((void**)&qTh, g_qTh); cudaGetSymbolAddress((void**)&qTl, g_qTl);
    cudaGetSymbolAddress((void**)&kTh, g_kTh); cudaGetSymbolAddress((void**)&kTl, g_kTl);
    cudaGetSymbolAddress((void**)&vTh, g_vTh); cudaGetSymbolAddress((void**)&vTl, g_vTl);
    cudaGetSymbolAddress((void**)&qGh, g_qGh); cudaGetSymbolAddress((void**)&qGl, g_qGl);
    cudaGetSymbolAddress((void**)&kGh, g_kGh); cudaGetSymbolAddress((void**)&kGl, g_kGl);
    cudaGetSymbolAddress((void**)&vGh, g_vGh); cudaGetSymbolAddress((void**)&vGl, g_vGl);

    cudaFuncSetAttribute(gemm_hmma, cudaFuncAttributeMaxDynamicSharedMemorySize, SMEMB);
    cudaFuncSetAttribute(fattn, cudaFuncAttributeMaxDynamicSharedMemorySize, ASMEM);

    const float scl = 0.125f;

    // ---- fused split of all 6 fp32 inputs ----
    int nTok = BB*SL*DM/4, nGlb = BB*GG*DM/4, nW = DM*DM/4;
    SplitJobs sj;
    sj.j[0] = { tok,  tokh,  tokl,  nTok };
    sj.j[1] = { glob, globh, globl, nGlb };
    sj.j[2] = { Wq, wqh, wql, nW };
    sj.j[3] = { Wk, wkh, wkl, nW };
    sj.j[4] = { Wv, wvh, wvl, nW };
    sj.j[5] = { Wo, woh, wol, nW };
    dim3 gSpl((nTok + 255) / 256, 6);
    split_all_kernel<<<gSpl, 256>>>(sj);

    GemmOp opQ  = {wqh, wql, qTh, qTl, 0, scl};
    GemmOp opK  = {wkh, wkl, kTh, kTl, 0, 1.f};
    GemmOp opV  = {wvh, wvl, vTh, vTl, 0, 1.f};
    GemmOp opQg = {wqh, wql, qGh, qGl, 0, scl};
    GemmOp opKg = {wkh, wkl, kGh, kGl, 0, 1.f};
    GemmOp opVg = {wvh, wvl, vGh, vGl, 0, 1.f};

    // ---- projections -> split bf16 head-split ----
    dim3 gTok(DM/128, (BB*SL)/128, 3);
    dim3 gGlb(DM/128, (BB*GG)/128, 3);
    gemm_hmma<<<gTok, 512, SMEMB>>>(tokh,  tokl,  opQ,  opK,  opV,  SL);
    gemm_hmma<<<gGlb, 512, SMEMB>>>(globh, globl, opQg, opKg, opVg, GG);

    // ---- flash attention (split-bf16 out) ----
    dim3 gridL(BB*NH*NBL, KBL/128);      // 256 x 4
    fattn<<<gridL, 256, ASMEM>>>(qTh, qTl, kGh, kGl, vGh, vGl,
                                 kTh, kTl, vTh, vTl, mask, aLh, aLl,
                                 NBL, KBL, GG + KBL);
    dim3 gridGA(BB*NH, 1);               // 32 x 1
    fattn<<<gridGA, 256, ASMEM>>>(qGh, qGl, kGh, kGl, vGh, vGl,
                                  kTh, kTl, vTh, vTl, mask, aGh, aGl,
                                  1, GG, GG + SL);

    // ---- output projections ----
    GemmOp opOL = {woh, wol, 0, 0, out, 1.f};
    GemmOp opOG = {woh, wol, 0, 0, out + (size_t)BB*SL*DM, 1.f};
    dim3 gOL(DM/128, (BB*SL)/128, 1);
    dim3 gOG(DM/128, (BB*GG)/128, 1);
    gemm_hmma<<<gOL, 512, SMEMB>>>(aLh, aLl, opOL, opOL, opOL, 0);
    gemm_hmma<<<gOG, 512, SMEMB>>>(aGh, aGl, opOG, opOG, opOG, 0);
}

// round 12
// speedup vs baseline: 1.1413x; 1.1413x over previous
#include <cuda_runtime.h>
#include <cuda_bf16.h>
#include <math.h>
#include <stdint.h>

// ---------------- problem constants ----------------
#define BB   2      // batch
#define SL   4096   // token seq len
#define GG   128    // global tokens
#define DM   1024   // embed dim
#define NH   16     // heads
#define FF   64     // head dim
#define NBL  8      // local blocks per seq
#define KBL  512    // block size
#define NSPLIT 4    // split-K factor for global attention

typedef __nv_bfloat16 bf16;

// ---------------- scratch (static device, no allocation) ----------------
// split-bf16 operands
__device__ bf16 g_tokh[(size_t)BB*SL*DM],  g_tokl[(size_t)BB*SL*DM];
__device__ bf16 g_globh[(size_t)BB*GG*DM], g_globl[(size_t)BB*GG*DM];
__device__ bf16 g_wqh[(size_t)DM*DM], g_wql[(size_t)DM*DM];
__device__ bf16 g_wkh[(size_t)DM*DM], g_wkl[(size_t)DM*DM];
__device__ bf16 g_wvh[(size_t)DM*DM], g_wvl[(size_t)DM*DM];
__device__ bf16 g_woh[(size_t)DM*DM], g_wol[(size_t)DM*DM];
__device__ bf16 g_aLh[(size_t)BB*SL*DM],  g_aLl[(size_t)BB*SL*DM];
__device__ bf16 g_aGh[(size_t)BB*GG*DM],  g_aGl[(size_t)BB*GG*DM];

// head-split projections [B,H,L,F], bf16 hi/lo
__device__ bf16 g_qTh[(size_t)BB*NH*SL*FF], g_qTl[(size_t)BB*NH*SL*FF];
__device__ bf16 g_kTh[(size_t)BB*NH*SL*FF], g_kTl[(size_t)BB*NH*SL*FF];
__device__ bf16 g_vTh[(size_t)BB*NH*SL*FF], g_vTl[(size_t)BB*NH*SL*FF];
__device__ bf16 g_qGh[(size_t)BB*NH*GG*FF], g_qGl[(size_t)BB*NH*GG*FF];
__device__ bf16 g_kGh[(size_t)BB*NH*GG*FF], g_kGl[(size_t)BB*NH*GG*FF];
__device__ bf16 g_vGh[(size_t)BB*NH*GG*FF], g_vGl[(size_t)BB*NH*GG*FF];

// split-K partials for global attention: [bh(32)][split(4)][q(128)] x {O[64] fp32, (m,l)}
__device__ float g_pO[(size_t)BB*NH*NSPLIT*GG*FF];
__device__ float g_pML[(size_t)BB*NH*NSPLIT*GG*2];

// ---------------- helpers (base-target ISA only) ----------------
__device__ __forceinline__ uint32_t smem_to_u32(const void* p) {
    uint32_t a;
    asm("{ .reg .u64 t; cvta.to.shared.u64 t, %1; cvt.u32.u64 %0, t; }" : "=r"(a) : "l"(p));
    return a;
}
#define CP_ASYNC16(saddr, gptr) \
    asm volatile("cp.async.cg.shared.global [%0], [%1], 16;" :: "r"(saddr), "l"(gptr))
#define CP_COMMIT() asm volatile("cp.async.commit_group;" ::: "memory")
#define CP_WAIT1()  asm volatile("cp.async.wait_group 1;" ::: "memory")
#define CP_WAIT0()  asm volatile("cp.async.wait_group 0;" ::: "memory")

#define LDMX4(d0, d1, d2, d3, addr) \
    asm volatile("ldmatrix.sync.aligned.m8n8.x4.shared.b16 {%0,%1,%2,%3}, [%4];" \
        : "=r"(d0), "=r"(d1), "=r"(d2), "=r"(d3) : "r"(addr))
#define LDMT4(d0, d1, d2, d3, addr) \
    asm volatile("ldmatrix.sync.aligned.m8n8.x4.trans.shared.b16 {%0,%1,%2,%3}, [%4];" \
        : "=r"(d0), "=r"(d1), "=r"(d2), "=r"(d3) : "r"(addr))

#define MMA_BF16(c, a, b) \
    asm volatile("mma.sync.aligned.m16n8k16.row.col.f32.bf16.bf16.f32 " \
        "{%0,%1,%2,%3}, {%4,%5,%6,%7}, {%8,%9}, {%0,%1,%2,%3};" \
        : "+f"((c)[0]), "+f"((c)[1]), "+f"((c)[2]), "+f"((c)[3]) \
        : "r"((a)[0]), "r"((a)[1]), "r"((a)[2]), "r"((a)[3]), \
          "r"((b)[0]), "r"((b)[1]))

__device__ __forceinline__ uint32_t pack_bf16x2(float x, float y) {
    __nv_bfloat162 t = __floats2bfloat162_rn(x, y);
    return *reinterpret_cast<uint32_t*>(&t);
}

// ---------------- fused split fp32 -> bf16 hi/lo ----------------
struct SplitJob { const float* x; bf16* hi; bf16* lo; int n4; };
struct SplitJobs { SplitJob j[6]; };

__global__ __launch_bounds__(256) void split_all_kernel(SplitJobs jobs)
{
    SplitJob jb = jobs.j[blockIdx.y];
    int i = blockIdx.x * 256 + threadIdx.x;
    if (i >= jb.n4) return;
    float4 v = ((const float4*)jb.x)[i];
    __nv_bfloat162 h0 = __floats2bfloat162_rn(v.x, v.y);
    __nv_bfloat162 h1 = __floats2bfloat162_rn(v.z, v.w);
    float rx = v.x - __bfloat162float(__low2bfloat16(h0));
    float ry = v.y - __bfloat162float(__high2bfloat16(h0));
    float rz = v.z - __bfloat162float(__low2bfloat16(h1));
    float rw = v.w - __bfloat162float(__high2bfloat16(h1));
    ((__nv_bfloat162*)jb.hi)[2*i]   = h0;
    ((__nv_bfloat162*)jb.hi)[2*i+1] = h1;
    ((__nv_bfloat162*)jb.lo)[2*i]   = __floats2bfloat162_rn(rx, ry);
    ((__nv_bfloat162*)jb.lo)[2*i+1] = __floats2bfloat162_rn(rz, rw);
}

// ---------------- mma.sync split-bf16 GEMM (R8-best config) ----------------
// 256 threads, 8 warps (4M x 2N), warp tile 32x64; 128x128 CTA tile; BK=32.
// 2-stage cp.async pipeline (80KB smem). C = Ah*Wh + Ah*Wl + Al*Wh.
struct GemmOp {
    const bf16 *Wh, *Wl;
    bf16 *Ch, *Cl;
    float* Cf;
    float scale;
};

#define ROWB    80
#define TILEB   (128 * ROWB)
#define STAGEB  (4 * TILEB)
#define SMEMB   (2 * STAGEB)     // 81920

__global__ __launch_bounds__(256, 1) void gemm_hmma(
    const bf16* __restrict__ Ah, const bf16* __restrict__ Al,
    GemmOp op0, GemmOp op1, GemmOp op2, int Lhead)
{
    extern __shared__ __align__(128) char smem[];
    const uint32_t sbase = smem_to_u32(smem);
    const int tid  = threadIdx.x;
    const int wid  = tid >> 5;
    const int lane = tid & 31;
    const int warpM = wid & 3, warpN = wid >> 2;
    const int m0 = blockIdx.y * 128;
    const int e0 = blockIdx.x * 128;

    GemmOp op = (blockIdx.z == 0) ? op0 : ((blockIdx.z == 1) ? op1 : op2);

    const bf16* srcs[4] = {
        Ah + (size_t)m0 * DM, Al + (size_t)m0 * DM,
        op.Wh + (size_t)e0 * DM, op.Wl + (size_t)e0 * DM };

    float acc[2][8][4];
    #pragma unroll
    for (int i = 0; i < 2; i++)
        #pragma unroll
        for (int j = 0; j < 8; j++)
            #pragma unroll
            for (int k = 0; k < 4; k++) acc[i][j][k] = 0.f;

    auto issue = [&](int stg, int k0) {
        uint32_t sb = sbase + stg * STAGEB;
        #pragma unroll
        for (int i = 0; i < 8; i++) {
            int c = tid + i * 256;
            int t = c >> 9, u = c & 511;
            int row = u >> 2, seg = u & 3;
            const bf16* g = srcs[t] + (size_t)row * DM + k0 + seg * 8;
            CP_ASYNC16(sb + t * TILEB + row * ROWB + seg * 16, g);
        }
    };

    issue(0, 0);
    CP_COMMIT();

    #pragma unroll 1
    for (int it = 0; it < 32; it++) {
        if (it + 1 < 32) {
            issue((it + 1) & 1, (it + 1) * 32);
            CP_COMMIT();
            CP_WAIT1();
        } else {
            CP_WAIT0();
        }
        __syncthreads();

        const uint32_t sb  = sbase + (it & 1) * STAGEB;
        const uint32_t sAh = sb;
        const uint32_t sAl = sb + TILEB;
        const uint32_t sBh = sb + 2 * TILEB;
        const uint32_t sBl = sb + 3 * TILEB;

        #pragma unroll
        for (int ks = 0; ks < 2; ks++) {
            uint32_t ah[2][4], al[2][4];
            {
                int r = lane & 15, c8 = lane >> 4;
                #pragma unroll
                for (int mf = 0; mf < 2; mf++) {
                    uint32_t off = (uint32_t)(warpM * 32 + mf * 16 + r) * ROWB
                                 + (uint32_t)(ks * 16 + c8 * 8) * 2;
                    LDMX4(ah[mf][0], ah[mf][1], ah[mf][2], ah[mf][3], sAh + off);
                    LDMX4(al[mf][0], al[mf][1], al[mf][2], al[mf][3], sAl + off);
                }
            }
            uint32_t bh[8][2], bl[8][2];
            {
                int rr = lane & 7, sub = lane >> 3;
                #pragma unroll
                for (int nf2 = 0; nf2 < 4; nf2++) {
                    int n  = warpN * 64 + nf2 * 16 + ((sub >> 1) << 3) + rr;
                    int kk = ks * 16 + ((sub & 1) << 3);
                    uint32_t off = (uint32_t)n * ROWB + (uint32_t)kk * 2;
                    LDMX4(bh[2*nf2][0], bh[2*nf2][1], bh[2*nf2+1][0], bh[2*nf2+1][1], sBh + off);
                    LDMX4(bl[2*nf2][0], bl[2*nf2][1], bl[2*nf2+1][0], bl[2*nf2+1][1], sBl + off);
                }
            }
            #pragma unroll
            for (int mf = 0; mf < 2; mf++)
                #pragma unroll
                for (int nf = 0; nf < 8; nf++) {
                    MMA_BF16(acc[mf][nf], ah[mf], bh[nf]);
                    MMA_BF16(acc[mf][nf], ah[mf], bl[nf]);
                    MMA_BF16(acc[mf][nf], al[mf], bh[nf]);
                }
        }
        __syncthreads();
    }

    #pragma unroll
    for (int mf = 0; mf < 2; mf++) {
        #pragma unroll
        for (int nf = 0; nf < 8; nf++) {
            int rbase = m0 + warpM * 32 + mf * 16 + (lane >> 2);
            int e = e0 + warpN * 64 + nf * 8 + (lane & 3) * 2;
            #pragma unroll
            for (int half = 0; half < 2; half++) {
                int m = rbase + half * 8;
                float vx = acc[mf][nf][half * 2 + 0] * op.scale;
                float vy = acc[mf][nf][half * 2 + 1] * op.scale;
                if (Lhead > 0) {
                    int bI = m / Lhead, l = m - bI * Lhead;
                    size_t idx = ((((size_t)bI * NH + (e >> 6)) * (size_t)Lhead + l) << 6) + (e & 63);
                    __nv_bfloat162 hi = __floats2bfloat162_rn(vx, vy);
                    float lx = vx - __bfloat162float(__low2bfloat16(hi));
                    float ly = vy - __bfloat162float(__high2bfloat16(hi));
                    *(__nv_bfloat162*)&op.Ch[idx] = hi;
                    *(__nv_bfloat162*)&op.Cl[idx] = __floats2bfloat162_rn(lx, ly);
                } else {
                    float2 v; v.x = vx; v.y = vy;
                    *(float2*)&op.Cf[(size_t)m * DM + e] = v;
                }
            }
        }
    }
}

// ---------------- flash attention (HMMA, split-bf16; optional split-K) ----------------
// nsplit==1: blockIdx.y = q-block, full pass, write normalized split-bf16 out.
// nsplit>1 : blockIdx.y = key-split, write fp32 partials (O, m, l) to pO/pML.
#define QROW     144
#define AQH_OFF  0
#define AQL_OFF  18432
#define AKV_OFF  36864
#define AKV_ARR  9216
#define AKV_BUF  36864
#define AMSK_OFF 110592
#define ASMEM    111104

__global__ __launch_bounds__(256, 1) void fattn(
    const bf16* __restrict__ Qh, const bf16* __restrict__ Ql,
    const bf16* __restrict__ KGh, const bf16* __restrict__ KGl,
    const bf16* __restrict__ VGh, const bf16* __restrict__ VGl,
    const bf16* __restrict__ KTh, const bf16* __restrict__ KTl,
    const bf16* __restrict__ VTh, const bf16* __restrict__ VTl,
    const float* __restrict__ mask,
    bf16* __restrict__ outh, bf16* __restrict__ outl,
    float* __restrict__ pO, float* __restrict__ pML,
    int NB, int QL, int X, int nsplit)
{
    extern __shared__ __align__(128) char smem[];
    const uint32_t sbase = smem_to_u32(smem);
    const int tid  = threadIdx.x;
    const int wid  = tid >> 5;
    const int lane = tid & 31;
    const int bh = blockIdx.x / NB;
    const int n  = blockIdx.x - bh * NB;
    const int b  = bh >> 4, h = bh & 15;
    const int LTOT = NB * QL;
    const int LO   = n * QL;
    const int T    = X >> 6;

    int split, qb;
    if (nsplit > 1) { split = blockIdx.y; qb = 0; }
    else            { split = 0;          qb = blockIdx.y; }
    const int tper = T / nsplit, trem = T - tper * nsplit;
    const int tile0  = split * tper + (split < trem ? split : trem);
    const int ntiles = tper + (split < trem ? 1 : 0);
    const int q0 = n * QL + qb * 128;

    const bf16* gk[4] = { KGh, KGl, VGh, VGl };
    const bf16* tk[4] = { KTh, KTl, VTh, VTl };

    auto issueKV = [&](int stg, int tile) {
        int xb = tile * 64;
        uint32_t sb = sbase + AKV_OFF + stg * AKV_BUF;
        #pragma unroll
        for (int i = 0; i < 8; i++) {
            int c = tid + i * 256;
            int arr = c >> 9, u = c & 511;
            int row = u >> 3, seg = u & 7;
            int x = xb + row;
            const bf16* src = (x < GG)
                ? gk[arr] + (((size_t)bh * GG + x) << 6) + seg * 8
                : tk[arr] + (((size_t)bh * SL + (x - GG + LO)) << 6) + seg * 8;
            CP_ASYNC16(sb + arr * AKV_ARR + row * QROW + seg * 16, src);
        }
        if (tid < 64) {
            int x = xb + tid;
            float mv = (x < GG) ? 0.f : mask[(size_t)b * SL + x - GG + LO];
            *(float*)(smem + AMSK_OFF + stg * 256 + tid * 4) = mv;
        }
    };

    #pragma unroll
    for (int i = 0; i < 8; i++) {
        int c = tid + i * 256;
        int arr = c >> 10, u = c & 1023;
        int row = u >> 3, seg = u & 7;
        const bf16* src = (arr ? Ql : Qh) + (((size_t)bh * LTOT + q0 + row) << 6) + seg * 8;
        CP_ASYNC16(sbase + (arr ? AQL_OFF : AQH_OFF) + row * QROW + seg * 16, src);
    }
    issueKV(0, tile0);
    CP_COMMIT();

    float o[8][4];
    #pragma unroll
    for (int i = 0; i < 8; i++)
        #pragma unroll
        for (int j = 0; j < 4; j++) o[i][j] = 0.f;
    float runA = -INFINITY, runB = -INFINITY, lA = 0.f, lB = 0.f;

    const int r = lane & 15, c8 = lane >> 4;
    const int rr = lane & 7, sub = lane >> 3;

    #pragma unroll 1
    for (int t = 0; t < ntiles; t++) {
        if (t + 1 < ntiles) {
            issueKV((t + 1) & 1, tile0 + t + 1);
            CP_COMMIT();
            CP_WAIT1();
        } else {
            CP_WAIT0();
        }
        __syncthreads();

        const uint32_t kvb = sbase + AKV_OFF + (t & 1) * AKV_BUF;
        const uint32_t sKh = kvb, sKl = kvb + AKV_ARR;
        const uint32_t sVh = kvb + 2 * AKV_ARR, sVl = kvb + 3 * AKV_ARR;
        const char* msk = smem + AMSK_OFF + (t & 1) * 256;

        float s[8][4];
        #pragma unroll
        for (int i = 0; i < 8; i++)
            #pragma unroll
            for (int j = 0; j < 4; j++) s[i][j] = 0.f;

        #pragma unroll
        for (int ks = 0; ks < 4; ks++) {
            uint32_t qh4[4], ql4[4];
            uint32_t qoff = (uint32_t)(wid * 16 + r) * QROW + (uint32_t)(ks * 16 + c8 * 8) * 2;
            LDMX4(qh4[0], qh4[1], qh4[2], qh4[3], sbase + AQH_OFF + qoff);
            LDMX4(ql4[0], ql4[1], ql4[2], ql4[3], sbase + AQL_OFF + qoff);
            uint32_t kh8[8][2], kl8[8][2];
            #pragma unroll
            for (int nf2 = 0; nf2 < 4; nf2++) {
                uint32_t boff = (uint32_t)(nf2 * 16 + ((sub >> 1) << 3) + rr) * QROW
                              + (uint32_t)(ks * 16 + ((sub & 1) << 3)) * 2;
                LDMX4(kh8[2*nf2][0], kh8[2*nf2][1], kh8[2*nf2+1][0], kh8[2*nf2+1][1], sKh + boff);
                LDMX4(kl8[2*nf2][0], kl8[2*nf2][1], kl8[2*nf2+1][0], kl8[2*nf2+1][1], sKl + boff);
            }
            #pragma unroll
            for (int nf = 0; nf < 8; nf++) {
                MMA_BF16(s[nf], qh4, kh8[nf]);
                MMA_BF16(s[nf], qh4, kl8[nf]);
                MMA_BF16(s[nf], ql4, kh8[nf]);
            }
        }

        #pragma unroll
        for (int nf = 0; nf < 8; nf++) {
            float2 mv = *(const float2*)(msk + (nf * 8 + (lane & 3) * 2) * 4);
            s[nf][0] += mv.x; s[nf][1] += mv.y;
            s[nf][2] += mv.x; s[nf][3] += mv.y;
        }
        float mA = -INFINITY, mB = -INFINITY;
        #pragma unroll
        for (int nf = 0; nf < 8; nf++) {
            mA = fmaxf(mA, fmaxf(s[nf][0], s[nf][1]));
            mB = fmaxf(mB, fmaxf(s[nf][2], s[nf][3]));
        }
        mA = fmaxf(mA, __shfl_xor_sync(0xffffffffu, mA, 1));
        mA = fmaxf(mA, __shfl_xor_sync(0xffffffffu, mA, 2));
        mB = fmaxf(mB, __shfl_xor_sync(0xffffffffu, mB, 1));
        mB = fmaxf(mB, __shfl_xor_sync(0xffffffffu, mB, 2));
        float nA = fmaxf(runA, mA), nB = fmaxf(runB, mB);
        float cA = __expf(runA - nA), cB = __expf(runB - nB);
        runA = nA; runB = nB;

        uint32_t phA[8], phB[8], plA[8], plB[8];
        float sumA = 0.f, sumB = 0.f;
        #pragma unroll
        for (int nf = 0; nf < 8; nf++) {
            float p0 = __expf(s[nf][0] - nA), p1 = __expf(s[nf][1] - nA);
            float p2 = __expf(s[nf][2] - nB), p3 = __expf(s[nf][3] - nB);
            sumA += p0 + p1; sumB += p2 + p3;
            __nv_bfloat162 h01 = __floats2bfloat162_rn(p0, p1);
            __nv_bfloat162 h23 = __floats2bfloat162_rn(p2, p3);
            phA[nf] = *reinterpret_cast<uint32_t*>(&h01);
            phB[nf] = *reinterpret_cast<uint32_t*>(&h23);
            plA[nf] = pack_bf16x2(p0 - __bfloat162float(__low2bfloat16(h01)),
                                  p1 - __bfloat162float(__high2bfloat16(h01)));
            plB[nf] = pack_bf16x2(p2 - __bfloat162float(__low2bfloat16(h23)),
                                  p3 - __bfloat162float(__high2bfloat16(h23)));
        }
        sumA += __shfl_xor_sync(0xffffffffu, sumA, 1);
        sumA += __shfl_xor_sync(0xffffffffu, sumA, 2);
        sumB += __shfl_xor_sync(0xffffffffu, sumB, 1);
        sumB += __shfl_xor_sync(0xffffffffu, sumB, 2);
        lA = lA * cA + sumA;
        lB = lB * cB + sumB;
        #pragma unroll
        for (int i = 0; i < 8; i++) {
            o[i][0] *= cA; o[i][1] *= cA; o[i][2] *= cB; o[i][3] *= cB;
        }

        #pragma unroll
        for (int ks = 0; ks < 4; ks++) {
            uint32_t aH[4] = { phA[2*ks], phB[2*ks], phA[2*ks+1], phB[2*ks+1] };
            uint32_t aL4[4] = { plA[2*ks], plB[2*ks], plA[2*ks+1], plB[2*ks+1] };
            #pragma unroll
            for (int jf2 = 0; jf2 < 4; jf2++) {
                uint32_t voff = (uint32_t)(ks * 16 + r) * QROW + (uint32_t)(jf2 * 16 + c8 * 8) * 2;
                uint32_t vh4[4], vl4[4];
                LDMT4(vh4[0], vh4[1], vh4[2], vh4[3], sVh + voff);
                LDMT4(vl4[0], vl4[1], vl4[2], vl4[3], sVl + voff);
                uint32_t b0h[2] = { vh4[0], vh4[1] }, b1h[2] = { vh4[2], vh4[3] };
                uint32_t b0l[2] = { vl4[0], vl4[1] }, b1l[2] = { vl4[2], vl4[3] };
                MMA_BF16(o[2*jf2],   aH,  b0h);
                MMA_BF16(o[2*jf2],   aH,  b0l);
                MMA_BF16(o[2*jf2],   aL4, b0h);
                MMA_BF16(o[2*jf2+1], aH,  b1h);
                MMA_BF16(o[2*jf2+1], aH,  b1l);
                MMA_BF16(o[2*jf2+1], aL4, b1h);
            }
        }
        __syncthreads();
    }

    if (pO) {
        // split-K partial write: unnormalized fp32 O + (m, l) per row
        int pb = (bh * nsplit + split) * GG;
        int qA = wid * 16 + (lane >> 2);
        int qB = qA + 8;
        #pragma unroll
        for (int nf = 0; nf < 8; nf++) {
            int f = nf * 8 + (lane & 3) * 2;
            float2 vA; vA.x = o[nf][0]; vA.y = o[nf][1];
            float2 vB; vB.x = o[nf][2]; vB.y = o[nf][3];
            *(float2*)&pO[((size_t)(pb + qA)) * FF + f] = vA;
            *(float2*)&pO[((size_t)(pb + qB)) * FF + f] = vB;
        }
        if ((lane & 3) == 0) {
            pML[(size_t)(pb + qA) * 2 + 0] = runA;
            pML[(size_t)(pb + qA) * 2 + 1] = lA;
            pML[(size_t)(pb + qB) * 2 + 0] = runB;
            pML[(size_t)(pb + qB) * 2 + 1] = lB;
        }
        return;
    }

    float iA = 1.f / lA, iB = 1.f / lB;
    int rowA = q0 + wid * 16 + (lane >> 2);
    size_t baseA = ((size_t)b * LTOT + rowA) * DM + h * 64;
    size_t baseB = baseA + (size_t)8 * DM;
    #pragma unroll
    for (int nf = 0; nf < 8; nf++) {
        int f = nf * 8 + (lane & 3) * 2;
        float ax = o[nf][0] * iA, ay = o[nf][1] * iA;
        float bx = o[nf][2] * iB, by = o[nf][3] * iB;
        __nv_bfloat162 hA = __floats2bfloat162_rn(ax, ay);
        __nv_bfloat162 hB = __floats2bfloat162_rn(bx, by);
        *(__nv_bfloat162*)&outh[baseA + f] = hA;
        *(__nv_bfloat162*)&outh[baseB + f] = hB;
        *(__nv_bfloat162*)&outl[baseA + f] =
            __floats2bfloat162_rn(ax - __bfloat162float(__low2bfloat16(hA)),
                                  ay - __bfloat162float(__high2bfloat16(hA)));
        *(__nv_bfloat162*)&outl[baseB + f] =
            __floats2bfloat162_rn(bx - __bfloat162float(__low2bfloat16(hB)),
                                  by - __bfloat162float(__high2bfloat16(hB)));
    }
}

// ---------------- split-K reduction: combine NSPLIT partials per global query ----------------
// warp per (bh, q) row; lane handles features lane and lane+32.
__global__ __launch_bounds__(256) void reduce_splitk(
    const float* __restrict__ pO, const float* __restrict__ pML,
    bf16* __restrict__ outh, bf16* __restrict__ outl)
{
    int w = (blockIdx.x * 256 + threadIdx.x) >> 5;
    int lane = threadIdx.x & 31;
    if (w >= BB * NH * GG) return;
    int bh = w >> 7, q = w & (GG - 1);
    int b = bh >> 4, h = bh & 15;

    float mstar = -INFINITY;
    #pragma unroll
    for (int s = 0; s < NSPLIT; s++)
        mstar = fmaxf(mstar, pML[(size_t)((bh * NSPLIT + s) * GG + q) * 2]);

    float L = 0.f, o0 = 0.f, o1 = 0.f;
    #pragma unroll
    for (int s = 0; s < NSPLIT; s++) {
        size_t ridx = (size_t)(bh * NSPLIT + s) * GG + q;
        float ms = pML[ridx * 2 + 0];
        float ls = pML[ridx * 2 + 1];
        float c = __expf(ms - mstar);
        L  += ls * c;
        o0 += pO[ridx * FF + lane]      * c;
        o1 += pO[ridx * FF + lane + 32] * c;
    }
    float inv = 1.f / L;
    float v0 = o0 * inv, v1 = o1 * inv;

    size_t base = ((size_t)b * GG + q) * DM + h * 64;
    bf16 h0 = __float2bfloat16(v0);
    bf16 h1 = __float2bfloat16(v1);
    outh[base + lane]      = h0;
    outh[base + lane + 32] = h1;
    outl[base + lane]      = __float2bfloat16(v0 - __bfloat162float(h0));
    outl[base + lane + 32] = __float2bfloat16(v1 - __bfloat162float(h1));
}

// ---------------- host ----------------
extern "C" void kernel_launch(void* const* d_in, const int* in_sizes, int n_in,
                              void* d_out, int out_size)
{
    const float* tok  = (const float*)d_in[0];
    const float* glob = (const float*)d_in[1];
    const float* mask = (const float*)d_in[2];
    const float* Wq   = (const float*)d_in[3];
    const float* Wk   = (const float*)d_in[4];
    const float* Wv   = (const float*)d_in[5];
    const float* Wo   = (const float*)d_in[6];
    float* out = (float*)d_out;

    bf16 *tokh,*tokl,*globh,*globl,*wqh,*wql,*wkh,*wkl,*wvh,*wvl,*woh,*wol,*aLh,*aLl,*aGh,*aGl;
    cudaGetSymbolAddress((void**)&tokh, g_tokh);   cudaGetSymbolAddress((void**)&tokl, g_tokl);
    cudaGetSymbolAddress((void**)&globh, g_globh); cudaGetSymbolAddress((void**)&globl, g_globl);
    cudaGetSymbolAddress((void**)&wqh, g_wqh);     cudaGetSymbolAddress((void**)&wql, g_wql);
    cudaGetSymbolAddress((void**)&wkh, g_wkh);     cudaGetSymbolAddress((void**)&wkl, g_wkl);
    cudaGetSymbolAddress((void**)&wvh, g_wvh);     cudaGetSymbolAddress((void**)&wvl, g_wvl);
    cudaGetSymbolAddress((void**)&woh, g_woh);     cudaGetSymbolAddress((void**)&wol, g_wol);
    cudaGetSymbolAddress((void**)&aLh, g_aLh);     cudaGetSymbolAddress((void**)&aLl, g_aLl);
    cudaGetSymbolAddress((void**)&aGh, g_aGh);     cudaGetSymbolAddress((void**)&aGl, g_aGl);

    bf16 *qTh,*qTl,*kTh,*kTl,*vTh,*vTl,*qGh,*qGl,*kGh,*kGl,*vGh,*vGl;
    cudaGetSymbolAddress((void**)&qTh, g_qTh); cudaGetSymbolAddress((void**)&qTl, g_qTl);
    cudaGetSymbolAddress((void**)&kTh, g_kTh); cudaGetSymbolAddress((void**)&kTl, g_kTl);
    cudaGetSymbolAddress((void**)&vTh, g_vTh); cudaGetSymbolAddress((void**)&vTl, g_vTl);
    cudaGetSymbolAddress((void**)&qGh, g_qGh); cudaGetSymbolAddress((void**)&qGl, g_qGl);
    cudaGetSymbolAddress((void**)&kGh, g_kGh); cudaGetSymbolAddress((void**)&kGl, g_kGl);
    cudaGetSymbolAddress((void**)&vGh, g_vGh); cudaGetSymbolAddress((void**)&vGl, g_vGl);

    float *pO, *pML;
    cudaGetSymbolAddress((void**)&pO, g_pO);
    cudaGetSymbolAddress((void**)&pML, g_pML);

    cudaFuncSetAttribute(gemm_hmma, cudaFuncAttributeMaxDynamicSharedMemorySize, SMEMB);
    cudaFuncSetAttribute(fattn, cudaFuncAttributeMaxDynamicSharedMemorySize, ASMEM);

    const float scl = 0.125f;

    // ---- fused split of all 6 fp32 inputs ----
    int nTok = BB*SL*DM/4, nGlb = BB*GG*DM/4, nW = DM*DM/4;
    SplitJobs sj;
    sj.j[0] = { tok,  tokh,  tokl,  nTok };
    sj.j[1] = { glob, globh, globl, nGlb };
    sj.j[2] = { Wq, wqh, wql, nW };
    sj.j[3] = { Wk, wkh, wkl, nW };
    sj.j[4] = { Wv, wvh, wvl, nW };
    sj.j[5] = { Wo, woh, wol, nW };
    dim3 gSpl((nTok + 255) / 256, 6);
    split_all_kernel<<<gSpl, 256>>>(sj);

    GemmOp opQ  = {wqh, wql, qTh, qTl, 0, scl};
    GemmOp opK  = {wkh, wkl, kTh, kTl, 0, 1.f};
    GemmOp opV  = {wvh, wvl, vTh, vTl, 0, 1.f};
    GemmOp opQg = {wqh, wql, qGh, qGl, 0, scl};
    GemmOp opKg = {wkh, wkl, kGh, kGl, 0, 1.f};
    GemmOp opVg = {wvh, wvl, vGh, vGl, 0, 1.f};

    // ---- projections -> split bf16 head-split ----
    dim3 gTok(DM/128, (BB*SL)/128, 3);
    dim3 gGlb(DM/128, (BB*GG)/128, 3);
    gemm_hmma<<<gTok, 256, SMEMB>>>(tokh,  tokl,  opQ,  opK,  opV,  SL);
    gemm_hmma<<<gGlb, 256, SMEMB>>>(globh, globl, opQg, opKg, opVg, GG);

    // ---- local flash attention (full pass, split-bf16 out) ----
    dim3 gridL(BB*NH*NBL, KBL/128);      // 256 x 4
    fattn<<<gridL, 256, ASMEM>>>(qTh, qTl, kGh, kGl, vGh, vGl,
                                 kTh, kTl, vTh, vTl, mask, aLh, aLl,
                                 0, 0, NBL, KBL, GG + KBL, 1);

    // ---- global flash attention: split-K over key tiles ----
    dim3 gridGA(BB*NH, NSPLIT);          // 32 x 4 = 128 CTAs (one wave)
    fattn<<<gridGA, 256, ASMEM>>>(qGh, qGl, kGh, kGl, vGh, vGl,
                                  kTh, kTl, vTh, vTl, mask, 0, 0,
                                  pO, pML, 1, GG, GG + SL, NSPLIT);

    // ---- combine split-K partials ----
    int nRows = BB * NH * GG;            // 4096 warps
    reduce_splitk<<<(nRows * 32 + 255) / 256, 256>>>(pO, pML, aGh, aGl);

    // ---- output projections ----
    GemmOp opOL = {woh, wol, 0, 0, out, 1.f};
    GemmOp opOG = {woh, wol, 0, 0, out + (size_t)BB*SL*DM, 1.f};
    dim3 gOL(DM/128, (BB*SL)/128, 1);
    dim3 gOG(DM/128, (BB*GG)/128, 1);
    gemm_hmma<<<gOL, 256, SMEMB>>>(aLh, aLl, opOL, opOL, opOL, 0);
    gemm_hmma<<<gOG, 256, SMEMB>>>(aGh, aGl, opOG, opOG, opOG, 0);
}

// round 13
// speedup vs baseline: 1.8935x; 1.6591x over previous
#include <cuda_runtime.h>
#include <cuda_bf16.h>
#include <math.h>
#include <stdint.h>

// ---------------- problem constants ----------------
#define BB   2      // batch
#define SL   4096   // token seq len
#define GG   128    // global tokens
#define DM   1024   // embed dim
#define NH   16     // heads
#define FF   64     // head dim
#define NBL  8      // local blocks per seq
#define KBL  512    // block size
#define NSPLIT 4    // split-K factor for global attention

typedef __nv_bfloat16 bf16;

// ---------------- scratch (static device, no allocation) ----------------
// int8 dual-level quantized operands + per-row fp32 scales
__device__ int8_t g_tokA[(size_t)BB*SL*DM],  g_tokB[(size_t)BB*SL*DM];
__device__ float  g_tokS[(size_t)BB*SL];
__device__ int8_t g_globA[(size_t)BB*GG*DM], g_globB[(size_t)BB*GG*DM];
__device__ float  g_globS[(size_t)BB*GG];
__device__ int8_t g_wqA[(size_t)DM*DM], g_wqB[(size_t)DM*DM];
__device__ float  g_wqS[DM];
__device__ int8_t g_wkA[(size_t)DM*DM], g_wkB[(size_t)DM*DM];
__device__ float  g_wkS[DM];
__device__ int8_t g_wvA[(size_t)DM*DM], g_wvB[(size_t)DM*DM];
__device__ float  g_wvS[DM];
__device__ int8_t g_woA[(size_t)DM*DM], g_woB[(size_t)DM*DM];
__device__ float  g_woS[DM];
__device__ int8_t g_aLA[(size_t)BB*SL*DM], g_aLB[(size_t)BB*SL*DM];
__device__ float  g_aLS[(size_t)BB*SL];
__device__ int8_t g_aGA[(size_t)BB*GG*DM], g_aGB[(size_t)BB*GG*DM];
__device__ float  g_aGS[(size_t)BB*GG];

// attention outputs (fp32, [B,L,D])
__device__ float g_aL[(size_t)BB*SL*DM];
__device__ float g_aG[(size_t)BB*GG*DM];

// head-split projections [B,H,L,F], bf16 hi/lo (for attention)
__device__ bf16 g_qTh[(size_t)BB*NH*SL*FF], g_qTl[(size_t)BB*NH*SL*FF];
__device__ bf16 g_kTh[(size_t)BB*NH*SL*FF], g_kTl[(size_t)BB*NH*SL*FF];
__device__ bf16 g_vTh[(size_t)BB*NH*SL*FF], g_vTl[(size_t)BB*NH*SL*FF];
__device__ bf16 g_qGh[(size_t)BB*NH*GG*FF], g_qGl[(size_t)BB*NH*GG*FF];
__device__ bf16 g_kGh[(size_t)BB*NH*GG*FF], g_kGl[(size_t)BB*NH*GG*FF];
__device__ bf16 g_vGh[(size_t)BB*NH*GG*FF], g_vGl[(size_t)BB*NH*GG*FF];

// split-K partials for global attention
__device__ float g_pO[(size_t)BB*NH*NSPLIT*GG*FF];
__device__ float g_pML[(size_t)BB*NH*NSPLIT*GG*2];

// ---------------- helpers (base-target ISA only) ----------------
__device__ __forceinline__ uint32_t smem_to_u32(const void* p) {
    uint32_t a;
    asm("{ .reg .u64 t; cvta.to.shared.u64 t, %1; cvt.u32.u64 %0, t; }" : "=r"(a) : "l"(p));
    return a;
}
#define CP_ASYNC16(saddr, gptr) \
    asm volatile("cp.async.cg.shared.global [%0], [%1], 16;" :: "r"(saddr), "l"(gptr))
#define CP_COMMIT() asm volatile("cp.async.commit_group;" ::: "memory")
#define CP_WAIT1()  asm volatile("cp.async.wait_group 1;" ::: "memory")
#define CP_WAIT0()  asm volatile("cp.async.wait_group 0;" ::: "memory")

#define LDMX4(d0, d1, d2, d3, addr) \
    asm volatile("ldmatrix.sync.aligned.m8n8.x4.shared.b16 {%0,%1,%2,%3}, [%4];" \
        : "=r"(d0), "=r"(d1), "=r"(d2), "=r"(d3) : "r"(addr))
#define LDMT4(d0, d1, d2, d3, addr) \
    asm volatile("ldmatrix.sync.aligned.m8n8.x4.trans.shared.b16 {%0,%1,%2,%3}, [%4];" \
        : "=r"(d0), "=r"(d1), "=r"(d2), "=r"(d3) : "r"(addr))

#define MMA_BF16(c, a, b) \
    asm volatile("mma.sync.aligned.m16n8k16.row.col.f32.bf16.bf16.f32 " \
        "{%0,%1,%2,%3}, {%4,%5,%6,%7}, {%8,%9}, {%0,%1,%2,%3};" \
        : "+f"((c)[0]), "+f"((c)[1]), "+f"((c)[2]), "+f"((c)[3]) \
        : "r"((a)[0]), "r"((a)[1]), "r"((a)[2]), "r"((a)[3]), \
          "r"((b)[0]), "r"((b)[1]))

#define MMA_S8(c, a, b) \
    asm volatile("mma.sync.aligned.m16n8k32.row.col.s32.s8.s8.s32 " \
        "{%0,%1,%2,%3}, {%4,%5,%6,%7}, {%8,%9}, {%0,%1,%2,%3};" \
        : "+r"((c)[0]), "+r"((c)[1]), "+r"((c)[2]), "+r"((c)[3]) \
        : "r"((a)[0]), "r"((a)[1]), "r"((a)[2]), "r"((a)[3]), \
          "r"((b)[0]), "r"((b)[1]))

__device__ __forceinline__ uint32_t pack_bf16x2(float x, float y) {
    __nv_bfloat162 t = __floats2bfloat162_rn(x, y);
    return *reinterpret_cast<uint32_t*>(&t);
}

// ---------------- per-row dual-level int8 quantization ----------------
// x = s*a + (s/252)*b, a,b in [-126,126]; s = rowmax/126. Rows are 1024 wide.
struct QJob { const float* x; int8_t* qa; int8_t* qb; float* qs; int nrows; };
struct QJobs { QJob j[6]; };

__global__ __launch_bounds__(256) void quant_rows(QJobs jobs)
{
    QJob jb = jobs.j[blockIdx.y];
    int row = blockIdx.x;
    if (row >= jb.nrows) return;
    __shared__ float wmax[8];
    int tid = threadIdx.x;
    const float4 v = ((const float4*)(jb.x + (size_t)row * DM))[tid];
    float m = fmaxf(fmaxf(fabsf(v.x), fabsf(v.y)), fmaxf(fabsf(v.z), fabsf(v.w)));
    #pragma unroll
    for (int o = 16; o; o >>= 1) m = fmaxf(m, __shfl_xor_sync(0xffffffffu, m, o));
    if ((tid & 31) == 0) wmax[tid >> 5] = m;
    __syncthreads();
    if (tid < 8) {
        float t = wmax[tid];
        #pragma unroll
        for (int o = 4; o; o >>= 1) t = fmaxf(t, __shfl_xor_sync(0xffu, t, o));
        if (tid == 0) wmax[0] = t;
    }
    __syncthreads();
    float rowmax = fmaxf(wmax[0], 1e-20f);
    float s = rowmax * (1.f / 126.f);
    float inv = 126.f / rowmax;

    int a0 = __float2int_rn(v.x * inv), a1 = __float2int_rn(v.y * inv);
    int a2 = __float2int_rn(v.z * inv), a3 = __float2int_rn(v.w * inv);
    float f252 = 252.f * inv;
    int b0 = __float2int_rn((v.x - a0 * s) * f252);
    int b1 = __float2int_rn((v.y - a1 * s) * f252);
    int b2 = __float2int_rn((v.z - a2 * s) * f252);
    int b3 = __float2int_rn((v.w - a3 * s) * f252);

    char4 ca; ca.x = (char)a0; ca.y = (char)a1; ca.z = (char)a2; ca.w = (char)a3;
    char4 cb; cb.x = (char)b0; cb.y = (char)b1; cb.z = (char)b2; cb.w = (char)b3;
    ((char4*)(jb.qa + (size_t)row * DM))[tid] = ca;
    ((char4*)(jb.qb + (size_t)row * DM))[tid] = cb;
    if (tid == 0) jb.qs[row] = s;
}

// ---------------- int8 dual-level GEMM ----------------
// C[m,e] = sx[m]*sw[e]*(Sum a*c + Sum(a*d + b*c)/252), dropping b*d.
// CTA tile 128m x 64e, K-chunk 64 (2 x k32 MMA steps), 256 thr, 8 warps (4M x 2N),
// warp tile 32x32. 2-stage cp.async pipeline.
struct GemmOpQ {
    const int8_t *Wa, *Wb;
    const float* Ws;
    bf16 *Ch, *Cl;      // Lhead>0: split-bf16 head-split out
    float* Cf;          // Lhead==0: fp32 out
    float scale;
};

#define QROWB  80
#define ATILE  (128 * QROWB)     // 10240
#define BTILE  (64 * QROWB)      // 5120
#define QSTAGE (2 * ATILE + 2 * BTILE)   // 30720
#define QSMEM  (2 * QSTAGE)              // 61440

__global__ __launch_bounds__(256, 2) void gemm_s8(
    const int8_t* __restrict__ Aa, const int8_t* __restrict__ Ab,
    const float* __restrict__ As,
    GemmOpQ op0, GemmOpQ op1, GemmOpQ op2, int Lhead)
{
    extern __shared__ __align__(128) char smem[];
    const uint32_t sbase = smem_to_u32(smem);
    const int tid  = threadIdx.x;
    const int wid  = tid >> 5;
    const int lane = tid & 31;
    const int warpM = wid & 3, warpN = wid >> 2;   // 4M x 2N
    const int m0 = blockIdx.y * 128;
    const int e0 = blockIdx.x * 64;

    GemmOpQ op = (blockIdx.z == 0) ? op0 : ((blockIdx.z == 1) ? op1 : op2);

    const int8_t* srcA[2] = { Aa + (size_t)m0 * DM, Ab + (size_t)m0 * DM };
    const int8_t* srcW[2] = { op.Wa + (size_t)e0 * DM, op.Wb + (size_t)e0 * DM };

    int acc1[2][4][4], acc2[2][4][4];
    #pragma unroll
    for (int i = 0; i < 2; i++)
        #pragma unroll
        for (int j = 0; j < 4; j++)
            #pragma unroll
            for (int k = 0; k < 4; k++) { acc1[i][j][k] = 0; acc2[i][j][k] = 0; }

    // 1536 16B-chunks per stage / 256 threads = 6 each
    auto issue = [&](int stg, int k0) {
        uint32_t sb = sbase + stg * QSTAGE;
        #pragma unroll
        for (int i = 0; i < 6; i++) {
            int c = tid + i * 256;
            const int8_t* g;
            uint32_t dst;
            if (c < 1024) {
                int arr = c >> 9, u = c & 511;
                int row = u >> 2, seg = u & 3;
                g = srcA[arr] + (size_t)row * DM + k0 + seg * 16;
                dst = sb + arr * ATILE + row * QROWB + seg * 16;
            } else {
                int c2 = c - 1024;
                int arr = c2 >> 8, u = c2 & 255;
                int row = u >> 2, seg = u & 3;
                g = srcW[arr] + (size_t)row * DM + k0 + seg * 16;
                dst = sb + 2 * ATILE + arr * BTILE + row * QROWB + seg * 16;
            }
            CP_ASYNC16(dst, g);
        }
    };

    issue(0, 0);
    CP_COMMIT();

    const int r = lane & 15, c8 = lane >> 4;
    const int rr = lane & 7, sub = lane >> 3;

    #pragma unroll 1
    for (int it = 0; it < 16; it++) {
        if (it + 1 < 16) {
            issue((it + 1) & 1, (it + 1) * 64);
            CP_COMMIT();
            CP_WAIT1();
        } else {
            CP_WAIT0();
        }
        __syncthreads();

        const uint32_t sb  = sbase + (it & 1) * QSTAGE;
        const uint32_t sAa = sb;
        const uint32_t sAb = sb + ATILE;
        const uint32_t sWa = sb + 2 * ATILE;
        const uint32_t sWb = sb + 2 * ATILE + BTILE;

        #pragma unroll
        for (int ks = 0; ks < 2; ks++) {
            uint32_t aa[2][4], ab[2][4];
            #pragma unroll
            for (int mf = 0; mf < 2; mf++) {
                uint32_t off = (uint32_t)(warpM * 32 + mf * 16 + r) * QROWB
                             + (uint32_t)(ks * 32 + c8 * 16);
                LDMX4(aa[mf][0], aa[mf][1], aa[mf][2], aa[mf][3], sAa + off);
                LDMX4(ab[mf][0], ab[mf][1], ab[mf][2], ab[mf][3], sAb + off);
            }
            uint32_t ba[4][2], bb[4][2];
            #pragma unroll
            for (int nf2 = 0; nf2 < 2; nf2++) {
                int n  = warpN * 32 + nf2 * 16 + ((sub >> 1) << 3) + rr;
                uint32_t off = (uint32_t)n * QROWB + (uint32_t)(ks * 32 + (sub & 1) * 16);
                LDMX4(ba[2*nf2][0], ba[2*nf2][1], ba[2*nf2+1][0], ba[2*nf2+1][1], sWa + off);
                LDMX4(bb[2*nf2][0], bb[2*nf2][1], bb[2*nf2+1][0], bb[2*nf2+1][1], sWb + off);
            }
            #pragma unroll
            for (int mf = 0; mf < 2; mf++)
                #pragma unroll
                for (int nf = 0; nf < 4; nf++) {
                    MMA_S8(acc1[mf][nf], aa[mf], ba[nf]);
                    MMA_S8(acc2[mf][nf], aa[mf], bb[nf]);
                    MMA_S8(acc2[mf][nf], ab[mf], ba[nf]);
                }
        }
        __syncthreads();
    }

    // epilogue: val = sx[m]*sw[e]*(acc1 + acc2/252) * scale
    const float INV252 = 1.f / 252.f;
    #pragma unroll
    for (int mf = 0; mf < 2; mf++) {
        #pragma unroll
        for (int nf = 0; nf < 4; nf++) {
            int rbase = m0 + warpM * 32 + mf * 16 + (lane >> 2);
            int e = e0 + warpN * 32 + nf * 8 + (lane & 3) * 2;
            float swx = op.Ws[e], swy = op.Ws[e + 1];
            #pragma unroll
            for (int half = 0; half < 2; half++) {
                int m = rbase + half * 8;
                float sx = As[m] * op.scale;
                float vx = sx * swx * ((float)acc1[mf][nf][half*2+0] + (float)acc2[mf][nf][half*2+0] * INV252);
                float vy = sx * swy * ((float)acc1[mf][nf][half*2+1] + (float)acc2[mf][nf][half*2+1] * INV252);
                if (Lhead > 0) {
                    int bI = m / Lhead, l = m - bI * Lhead;
                    size_t idx = ((((size_t)bI * NH + (e >> 6)) * (size_t)Lhead + l) << 6) + (e & 63);
                    __nv_bfloat162 hi = __floats2bfloat162_rn(vx, vy);
                    float lx = vx - __bfloat162float(__low2bfloat16(hi));
                    float ly = vy - __bfloat162float(__high2bfloat16(hi));
                    *(__nv_bfloat162*)&op.Ch[idx] = hi;
                    *(__nv_bfloat162*)&op.Cl[idx] = __floats2bfloat162_rn(lx, ly);
                } else {
                    float2 v; v.x = vx; v.y = vy;
                    *(float2*)&op.Cf[(size_t)m * DM + e] = v;
                }
            }
        }
    }
}

// ---------------- flash attention (HMMA, split-bf16 in, fp32 out; optional split-K) ----------------
#define QROW     144
#define AQH_OFF  0
#define AQL_OFF  18432
#define AKV_OFF  36864
#define AKV_ARR  9216
#define AKV_BUF  36864
#define AMSK_OFF 110592
#define ASMEM    111104

__global__ __launch_bounds__(256, 1) void fattn(
    const bf16* __restrict__ Qh, const bf16* __restrict__ Ql,
    const bf16* __restrict__ KGh, const bf16* __restrict__ KGl,
    const bf16* __restrict__ VGh, const bf16* __restrict__ VGl,
    const bf16* __restrict__ KTh, const bf16* __restrict__ KTl,
    const bf16* __restrict__ VTh, const bf16* __restrict__ VTl,
    const float* __restrict__ mask,
    float* __restrict__ outF,
    float* __restrict__ pO, float* __restrict__ pML,
    int NB, int QL, int X, int nsplit)
{
    extern __shared__ __align__(128) char smem[];
    const uint32_t sbase = smem_to_u32(smem);
    const int tid  = threadIdx.x;
    const int wid  = tid >> 5;
    const int lane = tid & 31;
    const int bh = blockIdx.x / NB;
    const int n  = blockIdx.x - bh * NB;
    const int b  = bh >> 4, h = bh & 15;
    const int LTOT = NB * QL;
    const int LO   = n * QL;
    const int T    = X >> 6;

    int split, qb;
    if (nsplit > 1) { split = blockIdx.y; qb = 0; }
    else            { split = 0;          qb = blockIdx.y; }
    const int tper = T / nsplit, trem = T - tper * nsplit;
    const int tile0  = split * tper + (split < trem ? split : trem);
    const int ntiles = tper + (split < trem ? 1 : 0);
    const int q0 = n * QL + qb * 128;

    const bf16* gk[4] = { KGh, KGl, VGh, VGl };
    const bf16* tk[4] = { KTh, KTl, VTh, VTl };

    auto issueKV = [&](int stg, int tile) {
        int xb = tile * 64;
        uint32_t sb = sbase + AKV_OFF + stg * AKV_BUF;
        #pragma unroll
        for (int i = 0; i < 8; i++) {
            int c = tid + i * 256;
            int arr = c >> 9, u = c & 511;
            int row = u >> 3, seg = u & 7;
            int x = xb + row;
            const bf16* src = (x < GG)
                ? gk[arr] + (((size_t)bh * GG + x) << 6) + seg * 8
                : tk[arr] + (((size_t)bh * SL + (x - GG + LO)) << 6) + seg * 8;
            CP_ASYNC16(sb + arr * AKV_ARR + row * QROW + seg * 16, src);
        }
        if (tid < 64) {
            int x = xb + tid;
            float mv = (x < GG) ? 0.f : mask[(size_t)b * SL + x - GG + LO];
            *(float*)(smem + AMSK_OFF + stg * 256 + tid * 4) = mv;
        }
    };

    #pragma unroll
    for (int i = 0; i < 8; i++) {
        int c = tid + i * 256;
        int arr = c >> 10, u = c & 1023;
        int row = u >> 3, seg = u & 7;
        const bf16* src = (arr ? Ql : Qh) + (((size_t)bh * LTOT + q0 + row) << 6) + seg * 8;
        CP_ASYNC16(sbase + (arr ? AQL_OFF : AQH_OFF) + row * QROW + seg * 16, src);
    }
    issueKV(0, tile0);
    CP_COMMIT();

    float o[8][4];
    #pragma unroll
    for (int i = 0; i < 8; i++)
        #pragma unroll
        for (int j = 0; j < 4; j++) o[i][j] = 0.f;
    float runA = -INFINITY, runB = -INFINITY, lA = 0.f, lB = 0.f;

    const int r = lane & 15, c8 = lane >> 4;
    const int rr = lane & 7, sub = lane >> 3;

    #pragma unroll 1
    for (int t = 0; t < ntiles; t++) {
        if (t + 1 < ntiles) {
            issueKV((t + 1) & 1, tile0 + t + 1);
            CP_COMMIT();
            CP_WAIT1();
        } else {
            CP_WAIT0();
        }
        __syncthreads();

        const uint32_t kvb = sbase + AKV_OFF + (t & 1) * AKV_BUF;
        const uint32_t sKh = kvb, sKl = kvb + AKV_ARR;
        const uint32_t sVh = kvb + 2 * AKV_ARR, sVl = kvb + 3 * AKV_ARR;
        const char* msk = smem + AMSK_OFF + (t & 1) * 256;

        float s[8][4];
        #pragma unroll
        for (int i = 0; i < 8; i++)
            #pragma unroll
            for (int j = 0; j < 4; j++) s[i][j] = 0.f;

        #pragma unroll
        for (int ks = 0; ks < 4; ks++) {
            uint32_t qh4[4], ql4[4];
            uint32_t qoff = (uint32_t)(wid * 16 + r) * QROW + (uint32_t)(ks * 16 + c8 * 8) * 2;
            LDMX4(qh4[0], qh4[1], qh4[2], qh4[3], sbase + AQH_OFF + qoff);
            LDMX4(ql4[0], ql4[1], ql4[2], ql4[3], sbase + AQL_OFF + qoff);
            uint32_t kh8[8][2], kl8[8][2];
            #pragma unroll
            for (int nf2 = 0; nf2 < 4; nf2++) {
                uint32_t boff = (uint32_t)(nf2 * 16 + ((sub >> 1) << 3) + rr) * QROW
                              + (uint32_t)(ks * 16 + ((sub & 1) << 3)) * 2;
                LDMX4(kh8[2*nf2][0], kh8[2*nf2][1], kh8[2*nf2+1][0], kh8[2*nf2+1][1], sKh + boff);
                LDMX4(kl8[2*nf2][0], kl8[2*nf2][1], kl8[2*nf2+1][0], kl8[2*nf2+1][1], sKl + boff);
            }
            #pragma unroll
            for (int nf = 0; nf < 8; nf++) {
                MMA_BF16(s[nf], qh4, kh8[nf]);
                MMA_BF16(s[nf], qh4, kl8[nf]);
                MMA_BF16(s[nf], ql4, kh8[nf]);
            }
        }

        #pragma unroll
        for (int nf = 0; nf < 8; nf++) {
            float2 mv = *(const float2*)(msk + (nf * 8 + (lane & 3) * 2) * 4);
            s[nf][0] += mv.x; s[nf][1] += mv.y;
            s[nf][2] += mv.x; s[nf][3] += mv.y;
        }
        float mA = -INFINITY, mB = -INFINITY;
        #pragma unroll
        for (int nf = 0; nf < 8; nf++) {
            mA = fmaxf(mA, fmaxf(s[nf][0], s[nf][1]));
            mB = fmaxf(mB, fmaxf(s[nf][2], s[nf][3]));
        }
        mA = fmaxf(mA, __shfl_xor_sync(0xffffffffu, mA, 1));
        mA = fmaxf(mA, __shfl_xor_sync(0xffffffffu, mA, 2));
        mB = fmaxf(mB, __shfl_xor_sync(0xffffffffu, mB, 1));
        mB = fmaxf(mB, __shfl_xor_sync(0xffffffffu, mB, 2));
        float nA = fmaxf(runA, mA), nB = fmaxf(runB, mB);
        float cA = __expf(runA - nA), cB = __expf(runB - nB);
        runA = nA; runB = nB;

        uint32_t phA[8], phB[8], plA[8], plB[8];
        float sumA = 0.f, sumB = 0.f;
        #pragma unroll
        for (int nf = 0; nf < 8; nf++) {
            float p0 = __expf(s[nf][0] - nA), p1 = __expf(s[nf][1] - nA);
            float p2 = __expf(s[nf][2] - nB), p3 = __expf(s[nf][3] - nB);
            sumA += p0 + p1; sumB += p2 + p3;
            __nv_bfloat162 h01 = __floats2bfloat162_rn(p0, p1);
            __nv_bfloat162 h23 = __floats2bfloat162_rn(p2, p3);
            phA[nf] = *reinterpret_cast<uint32_t*>(&h01);
            phB[nf] = *reinterpret_cast<uint32_t*>(&h23);
            plA[nf] = pack_bf16x2(p0 - __bfloat162float(__low2bfloat16(h01)),
                                  p1 - __bfloat162float(__high2bfloat16(h01)));
            plB[nf] = pack_bf16x2(p2 - __bfloat162float(__low2bfloat16(h23)),
                                  p3 - __bfloat162float(__high2bfloat16(h23)));
        }
        sumA += __shfl_xor_sync(0xffffffffu, sumA, 1);
        sumA += __shfl_xor_sync(0xffffffffu, sumA, 2);
        sumB += __shfl_xor_sync(0xffffffffu, sumB, 1);
        sumB += __shfl_xor_sync(0xffffffffu, sumB, 2);
        lA = lA * cA + sumA;
        lB = lB * cB + sumB;
        #pragma unroll
        for (int i = 0; i < 8; i++) {
            o[i][0] *= cA; o[i][1] *= cA; o[i][2] *= cB; o[i][3] *= cB;
        }

        #pragma unroll
        for (int ks = 0; ks < 4; ks++) {
            uint32_t aH[4] = { phA[2*ks], phB[2*ks], phA[2*ks+1], phB[2*ks+1] };
            uint32_t aL4[4] = { plA[2*ks], plB[2*ks], plA[2*ks+1], plB[2*ks+1] };
            #pragma unroll
            for (int jf2 = 0; jf2 < 4; jf2++) {
                uint32_t voff = (uint32_t)(ks * 16 + r) * QROW + (uint32_t)(jf2 * 16 + c8 * 8) * 2;
                uint32_t vh4[4], vl4[4];
                LDMT4(vh4[0], vh4[1], vh4[2], vh4[3], sVh + voff);
                LDMT4(vl4[0], vl4[1], vl4[2], vl4[3], sVl + voff);
                uint32_t b0h[2] = { vh4[0], vh4[1] }, b1h[2] = { vh4[2], vh4[3] };
                uint32_t b0l[2] = { vl4[0], vl4[1] }, b1l[2] = { vl4[2], vl4[3] };
                MMA_BF16(o[2*jf2],   aH,  b0h);
                MMA_BF16(o[2*jf2],   aH,  b0l);
                MMA_BF16(o[2*jf2],   aL4, b0h);
                MMA_BF16(o[2*jf2+1], aH,  b1h);
                MMA_BF16(o[2*jf2+1], aH,  b1l);
                MMA_BF16(o[2*jf2+1], aL4, b1h);
            }
        }
        __syncthreads();
    }

    if (pO) {
        int pb = (bh * nsplit + split) * GG;
        int qA = wid * 16 + (lane >> 2);
        int qB = qA + 8;
        #pragma unroll
        for (int nf = 0; nf < 8; nf++) {
            int f = nf * 8 + (lane & 3) * 2;
            float2 vA; vA.x = o[nf][0]; vA.y = o[nf][1];
            float2 vB; vB.x = o[nf][2]; vB.y = o[nf][3];
            *(float2*)&pO[((size_t)(pb + qA)) * FF + f] = vA;
            *(float2*)&pO[((size_t)(pb + qB)) * FF + f] = vB;
        }
        if ((lane & 3) == 0) {
            pML[(size_t)(pb + qA) * 2 + 0] = runA;
            pML[(size_t)(pb + qA) * 2 + 1] = lA;
            pML[(size_t)(pb + qB) * 2 + 0] = runB;
            pML[(size_t)(pb + qB) * 2 + 1] = lB;
        }
        return;
    }

    float iA = 1.f / lA, iB = 1.f / lB;
    int rowA = q0 + wid * 16 + (lane >> 2);
    size_t baseA = ((size_t)b * LTOT + rowA) * DM + h * 64;
    size_t baseB = baseA + (size_t)8 * DM;
    #pragma unroll
    for (int nf = 0; nf < 8; nf++) {
        int f = nf * 8 + (lane & 3) * 2;
        float2 vA; vA.x = o[nf][0] * iA; vA.y = o[nf][1] * iA;
        float2 vB; vB.x = o[nf][2] * iB; vB.y = o[nf][3] * iB;
        *(float2*)&outF[baseA + f] = vA;
        *(float2*)&outF[baseB + f] = vB;
    }
}

// ---------------- split-K reduction (fp32 out) ----------------
__global__ __launch_bounds__(256) void reduce_splitk(
    const float* __restrict__ pO, const float* __restrict__ pML,
    float* __restrict__ outF)
{
    int w = (blockIdx.x * 256 + threadIdx.x) >> 5;
    int lane = threadIdx.x & 31;
    if (w >= BB * NH * GG) return;
    int bh = w >> 7, q = w & (GG - 1);
    int b = bh >> 4, h = bh & 15;

    float mstar = -INFINITY;
    #pragma unroll
    for (int s = 0; s < NSPLIT; s++)
        mstar = fmaxf(mstar, pML[(size_t)((bh * NSPLIT + s) * GG + q) * 2]);

    float L = 0.f, o0 = 0.f, o1 = 0.f;
    #pragma unroll
    for (int s = 0; s < NSPLIT; s++) {
        size_t ridx = (size_t)(bh * NSPLIT + s) * GG + q;
        float ms = pML[ridx * 2 + 0];
        float ls = pML[ridx * 2 + 1];
        float c = __expf(ms - mstar);
        L  += ls * c;
        o0 += pO[ridx * FF + lane]      * c;
        o1 += pO[ridx * FF + lane + 32] * c;
    }
    float inv = 1.f / L;
    size_t base = ((size_t)b * GG + q) * DM + h * 64;
    outF[base + lane]      = o0 * inv;
    outF[base + lane + 32] = o1 * inv;
}

// ---------------- host ----------------
extern "C" void kernel_launch(void* const* d_in, const int* in_sizes, int n_in,
                              void* d_out, int out_size)
{
    const float* tok  = (const float*)d_in[0];
    const float* glob = (const float*)d_in[1];
    const float* mask = (const float*)d_in[2];
    const float* Wq   = (const float*)d_in[3];
    const float* Wk   = (const float*)d_in[4];
    const float* Wv   = (const float*)d_in[5];
    const float* Wo   = (const float*)d_in[6];
    float* out = (float*)d_out;

    int8_t *tokA,*tokB,*globA,*globB,*wqA,*wqB,*wkA,*wkB,*wvA,*wvB,*woA,*woB,*aLA,*aLB,*aGA,*aGB;
    float *tokS,*globS,*wqS,*wkS,*wvS,*woS,*aLS,*aGS,*aLp,*aGp,*pO,*pML;
    cudaGetSymbolAddress((void**)&tokA, g_tokA);   cudaGetSymbolAddress((void**)&tokB, g_tokB);
    cudaGetSymbolAddress((void**)&tokS, g_tokS);
    cudaGetSymbolAddress((void**)&globA, g_globA); cudaGetSymbolAddress((void**)&globB, g_globB);
    cudaGetSymbolAddress((void**)&globS, g_globS);
    cudaGetSymbolAddress((void**)&wqA, g_wqA); cudaGetSymbolAddress((void**)&wqB, g_wqB);
    cudaGetSymbolAddress((void**)&wqS, g_wqS);
    cudaGetSymbolAddress((void**)&wkA, g_wkA); cudaGetSymbolAddress((void**)&wkB, g_wkB);
    cudaGetSymbolAddress((void**)&wkS, g_wkS);
    cudaGetSymbolAddress((void**)&wvA, g_wvA); cudaGetSymbolAddress((void**)&wvB, g_wvB);
    cudaGetSymbolAddress((void**)&wvS, g_wvS);
    cudaGetSymbolAddress((void**)&woA, g_woA); cudaGetSymbolAddress((void**)&woB, g_woB);
    cudaGetSymbolAddress((void**)&woS, g_woS);
    cudaGetSymbolAddress((void**)&aLA, g_aLA); cudaGetSymbolAddress((void**)&aLB, g_aLB);
    cudaGetSymbolAddress((void**)&aLS, g_aLS);
    cudaGetSymbolAddress((void**)&aGA, g_aGA); cudaGetSymbolAddress((void**)&aGB, g_aGB);
    cudaGetSymbolAddress((void**)&aGS, g_aGS);
    cudaGetSymbolAddress((void**)&aLp, g_aL);  cudaGetSymbolAddress((void**)&aGp, g_aG);
    cudaGetSymbolAddress((void**)&pO, g_pO);   cudaGetSymbolAddress((void**)&pML, g_pML);

    bf16 *qTh,*qTl,*kTh,*kTl,*vTh,*vTl,*qGh,*qGl,*kGh,*kGl,*vGh,*vGl;
    cudaGetSymbolAddress((void**)&qTh, g_qTh); cudaGetSymbolAddress((void**)&qTl, g_qTl);
    cudaGetSymbolAddress((void**)&kTh, g_kTh); cudaGetSymbolAddress((void**)&kTl, g_kTl);
    cudaGetSymbolAddress((void**)&vTh, g_vTh); cudaGetSymbolAddress((void**)&vTl, g_vTl);
    cudaGetSymbolAddress((void**)&qGh, g_qGh); cudaGetSymbolAddress((void**)&qGl, g_qGl);
    cudaGetSymbolAddress((void**)&kGh, g_kGh); cudaGetSymbolAddress((void**)&kGl, g_kGl);
    cudaGetSymbolAddress((void**)&vGh, g_vGh); cudaGetSymbolAddress((void**)&vGl, g_vGl);

    cudaFuncSetAttribute(gemm_s8, cudaFuncAttributeMaxDynamicSharedMemorySize, QSMEM);
    cudaFuncSetAttribute(fattn, cudaFuncAttributeMaxDynamicSharedMemorySize, ASMEM);

    const float scl = 0.125f;

    // ---- quantize all 6 fp32 inputs (per-row dual int8) ----
    QJobs qin;
    qin.j[0] = { tok,  tokA,  tokB,  tokS,  BB*SL };
    qin.j[1] = { glob, globA, globB, globS, BB*GG };
    qin.j[2] = { Wq, wqA, wqB, wqS, DM };
    qin.j[3] = { Wk, wkA, wkB, wkS, DM };
    qin.j[4] = { Wv, wvA, wvB, wvS, DM };
    qin.j[5] = { Wo, woA, woB, woS, DM };
    quant_rows<<<dim3(BB*SL, 6), 256>>>(qin);

    GemmOpQ opQ  = {wqA, wqB, wqS, qTh, qTl, 0, scl};
    GemmOpQ opK  = {wkA, wkB, wkS, kTh, kTl, 0, 1.f};
    GemmOpQ opV  = {wvA, wvB, wvS, vTh, vTl, 0, 1.f};
    GemmOpQ opQg = {wqA, wqB, wqS, qGh, qGl, 0, scl};
    GemmOpQ opKg = {wkA, wkB, wkS, kGh, kGl, 0, 1.f};
    GemmOpQ opVg = {wvA, wvB, wvS, vGh, vGl, 0, 1.f};

    // ---- projections -> split bf16 head-split ----
    dim3 gTok(DM/64, (BB*SL)/128, 3);    // 16 x 64 x 3
    dim3 gGlb(DM/64, (BB*GG)/128, 3);    // 16 x 2 x 3
    gemm_s8<<<gTok, 256, QSMEM>>>(tokA,  tokB,  tokS,  opQ,  opK,  opV,  SL);
    gemm_s8<<<gGlb, 256, QSMEM>>>(globA, globB, globS, opQg, opKg, opVg, GG);

    // ---- local flash attention (fp32 out) ----
    dim3 gridL(BB*NH*NBL, KBL/128);      // 256 x 4
    fattn<<<gridL, 256, ASMEM>>>(qTh, qTl, kGh, kGl, vGh, vGl,
                                 kTh, kTl, vTh, vTl, mask, aLp,
                                 0, 0, NBL, KBL, GG + KBL, 1);

    // ---- global flash attention: split-K ----
    dim3 gridGA(BB*NH, NSPLIT);          // 32 x 4
    fattn<<<gridGA, 256, ASMEM>>>(qGh, qGl, kGh, kGl, vGh, vGl,
                                  kTh, kTl, vTh, vTl, mask, 0,
                                  pO, pML, 1, GG, GG + SL, NSPLIT);
    int nRows = BB * NH * GG;
    reduce_splitk<<<(nRows * 32 + 255) / 256, 256>>>(pO, pML, aGp);

    // ---- quantize attention outputs ----
    QJobs qat;
    qat.j[0] = { aLp, aLA, aLB, aLS, BB*SL };
    qat.j[1] = { aGp, aGA, aGB, aGS, BB*GG };
    qat.j[2] = { aGp, aGA, aGB, aGS, 0 };
    qat.j[3] = { aGp, aGA, aGB, aGS, 0 };
    qat.j[4] = { aGp, aGA, aGB, aGS, 0 };
    qat.j[5] = { aGp, aGA, aGB, aGS, 0 };
    quant_rows<<<dim3(BB*SL, 2), 256>>>(qat);

    // ---- output projections (fp32 into d_out) ----
    GemmOpQ opOL = {woA, woB, woS, 0, 0, out, 1.f};
    GemmOpQ opOG = {woA, woB, woS, 0, 0, out + (size_t)BB*SL*DM, 1.f};
    dim3 gOL(DM/64, (BB*SL)/128, 1);
    dim3 gOG(DM/64, (BB*GG)/128, 1);
    gemm_s8<<<gOL, 256, QSMEM>>>(aLA, aLB, aLS, opOL, opOL, opOL, 0);
    gemm_s8<<<gOG, 256, QSMEM>>>(aGA, aGB, aGS, opOG, opOG, opOG, 0);
}

// round 15
// speedup vs baseline: 1.9753x; 1.0432x over previous
#include <cuda_runtime.h>
#include <cuda_bf16.h>
#include <math.h>
#include <stdint.h>

// ---------------- problem constants ----------------
#define BB   2      // batch
#define SL   4096   // token seq len
#define GG   128    // global tokens
#define DM   1024   // embed dim
#define NH   16     // heads
#define FF   64     // head dim
#define NBL  8      // local blocks per seq
#define KBL  512    // block size
#define NSPLIT 4    // split-K factor for global attention

typedef __nv_bfloat16 bf16;

// ---------------- scratch (static device, no allocation) ----------------
__device__ int8_t g_tokA[(size_t)BB*SL*DM],  g_tokB[(size_t)BB*SL*DM];
__device__ float  g_tokS[(size_t)BB*SL];
__device__ int8_t g_globA[(size_t)BB*GG*DM], g_globB[(size_t)BB*GG*DM];
__device__ float  g_globS[(size_t)BB*GG];
__device__ int8_t g_wqA[(size_t)DM*DM], g_wqB[(size_t)DM*DM];
__device__ float  g_wqS[DM];
__device__ int8_t g_wkA[(size_t)DM*DM], g_wkB[(size_t)DM*DM];
__device__ float  g_wkS[DM];
__device__ int8_t g_wvA[(size_t)DM*DM], g_wvB[(size_t)DM*DM];
__device__ float  g_wvS[DM];
__device__ int8_t g_woA[(size_t)DM*DM], g_woB[(size_t)DM*DM];
__device__ float  g_woS[DM];
__device__ int8_t g_aLA[(size_t)BB*SL*DM], g_aLB[(size_t)BB*SL*DM];
__device__ float  g_aLS[(size_t)BB*SL];
__device__ int8_t g_aGA[(size_t)BB*GG*DM], g_aGB[(size_t)BB*GG*DM];
__device__ float  g_aGS[(size_t)BB*GG];

__device__ float g_aL[(size_t)BB*SL*DM];
__device__ float g_aG[(size_t)BB*GG*DM];

__device__ bf16 g_qTh[(size_t)BB*NH*SL*FF], g_qTl[(size_t)BB*NH*SL*FF];
__device__ bf16 g_kTh[(size_t)BB*NH*SL*FF], g_kTl[(size_t)BB*NH*SL*FF];
__device__ bf16 g_vTh[(size_t)BB*NH*SL*FF], g_vTl[(size_t)BB*NH*SL*FF];
__device__ bf16 g_qGh[(size_t)BB*NH*GG*FF], g_qGl[(size_t)BB*NH*GG*FF];
__device__ bf16 g_kGh[(size_t)BB*NH*GG*FF], g_kGl[(size_t)BB*NH*GG*FF];
__device__ bf16 g_vGh[(size_t)BB*NH*GG*FF], g_vGl[(size_t)BB*NH*GG*FF];

__device__ float g_pO[(size_t)BB*NH*NSPLIT*GG*FF];
__device__ float g_pML[(size_t)BB*NH*NSPLIT*GG*2];

// ---------------- helpers (base-target ISA only) ----------------
__device__ __forceinline__ uint32_t smem_to_u32(const void* p) {
    uint32_t a;
    asm("{ .reg .u64 t; cvta.to.shared.u64 t, %1; cvt.u32.u64 %0, t; }" : "=r"(a) : "l"(p));
    return a;
}
#define CP_ASYNC16(saddr, gptr) \
    asm volatile("cp.async.cg.shared.global [%0], [%1], 16;" :: "r"(saddr), "l"(gptr))
#define CP_COMMIT() asm volatile("cp.async.commit_group;" ::: "memory")
#define CP_WAIT1()  asm volatile("cp.async.wait_group 1;" ::: "memory")
#define CP_WAIT0()  asm volatile("cp.async.wait_group 0;" ::: "memory")

#define LDMX4(d0, d1, d2, d3, addr) \
    asm volatile("ldmatrix.sync.aligned.m8n8.x4.shared.b16 {%0,%1,%2,%3}, [%4];" \
        : "=r"(d0), "=r"(d1), "=r"(d2), "=r"(d3) : "r"(addr))
#define LDMT4(d0, d1, d2, d3, addr) \
    asm volatile("ldmatrix.sync.aligned.m8n8.x4.trans.shared.b16 {%0,%1,%2,%3}, [%4];" \
        : "=r"(d0), "=r"(d1), "=r"(d2), "=r"(d3) : "r"(addr))

#define MMA_BF16(c, a, b) \
    asm volatile("mma.sync.aligned.m16n8k16.row.col.f32.bf16.bf16.f32 " \
        "{%0,%1,%2,%3}, {%4,%5,%6,%7}, {%8,%9}, {%0,%1,%2,%3};" \
        : "+f"((c)[0]), "+f"((c)[1]), "+f"((c)[2]), "+f"((c)[3]) \
        : "r"((a)[0]), "r"((a)[1]), "r"((a)[2]), "r"((a)[3]), \
          "r"((b)[0]), "r"((b)[1]))

#define MMA_S8(c, a, b) \
    asm volatile("mma.sync.aligned.m16n8k32.row.col.s32.s8.s8.s32 " \
        "{%0,%1,%2,%3}, {%4,%5,%6,%7}, {%8,%9}, {%0,%1,%2,%3};" \
        : "+r"((c)[0]), "+r"((c)[1]), "+r"((c)[2]), "+r"((c)[3]) \
        : "r"((a)[0]), "r"((a)[1]), "r"((a)[2]), "r"((a)[3]), \
          "r"((b)[0]), "r"((b)[1]))

__device__ __forceinline__ uint32_t pack_bf16x2(float x, float y) {
    __nv_bfloat162 t = __floats2bfloat162_rn(x, y);
    return *reinterpret_cast<uint32_t*>(&t);
}

// ---------------- per-row dual-level int8 quantization ----------------
struct QJob { const float* x; int8_t* qa; int8_t* qb; float* qs; int nrows; };
struct QJobs { QJob j[6]; };

__global__ __launch_bounds__(256) void quant_rows(QJobs jobs)
{
    QJob jb = jobs.j[blockIdx.y];
    int row = blockIdx.x;
    if (row >= jb.nrows) return;
    __shared__ float wmax[8];
    int tid = threadIdx.x;
    const float4 v = ((const float4*)(jb.x + (size_t)row * DM))[tid];
    float m = fmaxf(fmaxf(fabsf(v.x), fabsf(v.y)), fmaxf(fabsf(v.z), fabsf(v.w)));
    #pragma unroll
    for (int o = 16; o; o >>= 1) m = fmaxf(m, __shfl_xor_sync(0xffffffffu, m, o));
    if ((tid & 31) == 0) wmax[tid >> 5] = m;
    __syncthreads();
    if (tid < 8) {
        float t = wmax[tid];
        #pragma unroll
        for (int o = 4; o; o >>= 1) t = fmaxf(t, __shfl_xor_sync(0xffu, t, o));
        if (tid == 0) wmax[0] = t;
    }
    __syncthreads();
    float rowmax = fmaxf(wmax[0], 1e-20f);
    float s = rowmax * (1.f / 126.f);
    float inv = 126.f / rowmax;

    int a0 = __float2int_rn(v.x * inv), a1 = __float2int_rn(v.y * inv);
    int a2 = __float2int_rn(v.z * inv), a3 = __float2int_rn(v.w * inv);
    float f252 = 252.f * inv;
    int b0 = __float2int_rn((v.x - a0 * s) * f252);
    int b1 = __float2int_rn((v.y - a1 * s) * f252);
    int b2 = __float2int_rn((v.z - a2 * s) * f252);
    int b3 = __float2int_rn((v.w - a3 * s) * f252);

    char4 ca; ca.x = (char)a0; ca.y = (char)a1; ca.z = (char)a2; ca.w = (char)a3;
    char4 cb; cb.x = (char)b0; cb.y = (char)b1; cb.z = (char)b2; cb.w = (char)b3;
    ((char4*)(jb.qa + (size_t)row * DM))[tid] = ca;
    ((char4*)(jb.qb + (size_t)row * DM))[tid] = cb;
    if (tid == 0) jb.qs[row] = s;
}

// ---------------- int8 dual-level GEMM (R13 winner, unchanged) ----------------
struct GemmOpQ {
    const int8_t *Wa, *Wb;
    const float* Ws;
    bf16 *Ch, *Cl;
    float* Cf;
    float scale;
};

#define QROWB  80
#define ATILE  (128 * QROWB)
#define BTILE  (64 * QROWB)
#define QSTAGE (2 * ATILE + 2 * BTILE)
#define QSMEM  (2 * QSTAGE)

__global__ __launch_bounds__(256, 2) void gemm_s8(
    const int8_t* __restrict__ Aa, const int8_t* __restrict__ Ab,
    const float* __restrict__ As,
    GemmOpQ op0, GemmOpQ op1, GemmOpQ op2, int Lhead)
{
    extern __shared__ __align__(128) char smem[];
    const uint32_t sbase = smem_to_u32(smem);
    const int tid  = threadIdx.x;
    const int wid  = tid >> 5;
    const int lane = tid & 31;
    const int warpM = wid & 3, warpN = wid >> 2;
    const int m0 = blockIdx.y * 128;
    const int e0 = blockIdx.x * 64;

    GemmOpQ op = (blockIdx.z == 0) ? op0 : ((blockIdx.z == 1) ? op1 : op2);

    const int8_t* srcA[2] = { Aa + (size_t)m0 * DM, Ab + (size_t)m0 * DM };
    const int8_t* srcW[2] = { op.Wa + (size_t)e0 * DM, op.Wb + (size_t)e0 * DM };

    int acc1[2][4][4], acc2[2][4][4];
    #pragma unroll
    for (int i = 0; i < 2; i++)
        #pragma unroll
        for (int j = 0; j < 4; j++)
            #pragma unroll
            for (int k = 0; k < 4; k++) { acc1[i][j][k] = 0; acc2[i][j][k] = 0; }

    auto issue = [&](int stg, int k0) {
        uint32_t sb = sbase + stg * QSTAGE;
        #pragma unroll
        for (int i = 0; i < 6; i++) {
            int c = tid + i * 256;
            const int8_t* g;
            uint32_t dst;
            if (c < 1024) {
                int arr = c >> 9, u = c & 511;
                int row = u >> 2, seg = u & 3;
                g = srcA[arr] + (size_t)row * DM + k0 + seg * 16;
                dst = sb + arr * ATILE + row * QROWB + seg * 16;
            } else {
                int c2 = c - 1024;
                int arr = c2 >> 8, u = c2 & 255;
                int row = u >> 2, seg = u & 3;
                g = srcW[arr] + (size_t)row * DM + k0 + seg * 16;
                dst = sb + 2 * ATILE + arr * BTILE + row * QROWB + seg * 16;
            }
            CP_ASYNC16(dst, g);
        }
    };

    issue(0, 0);
    CP_COMMIT();

    const int r = lane & 15, c8 = lane >> 4;
    const int rr = lane & 7, sub = lane >> 3;

    #pragma unroll 1
    for (int it = 0; it < 16; it++) {
        if (it + 1 < 16) {
            issue((it + 1) & 1, (it + 1) * 64);
            CP_COMMIT();
            CP_WAIT1();
        } else {
            CP_WAIT0();
        }
        __syncthreads();

        const uint32_t sb  = sbase + (it & 1) * QSTAGE;
        const uint32_t sAa = sb;
        const uint32_t sAb = sb + ATILE;
        const uint32_t sWa = sb + 2 * ATILE;
        const uint32_t sWb = sb + 2 * ATILE + BTILE;

        #pragma unroll
        for (int ks = 0; ks < 2; ks++) {
            uint32_t aa[2][4], ab[2][4];
            #pragma unroll
            for (int mf = 0; mf < 2; mf++) {
                uint32_t off = (uint32_t)(warpM * 32 + mf * 16 + r) * QROWB
                             + (uint32_t)(ks * 32 + c8 * 16);
                LDMX4(aa[mf][0], aa[mf][1], aa[mf][2], aa[mf][3], sAa + off);
                LDMX4(ab[mf][0], ab[mf][1], ab[mf][2], ab[mf][3], sAb + off);
            }
            uint32_t ba[4][2], bb[4][2];
            #pragma unroll
            for (int nf2 = 0; nf2 < 2; nf2++) {
                int n  = warpN * 32 + nf2 * 16 + ((sub >> 1) << 3) + rr;
                uint32_t off = (uint32_t)n * QROWB + (uint32_t)(ks * 32 + (sub & 1) * 16);
                LDMX4(ba[2*nf2][0], ba[2*nf2][1], ba[2*nf2+1][0], ba[2*nf2+1][1], sWa + off);
                LDMX4(bb[2*nf2][0], bb[2*nf2][1], bb[2*nf2+1][0], bb[2*nf2+1][1], sWb + off);
            }
            #pragma unroll
            for (int mf = 0; mf < 2; mf++)
                #pragma unroll
                for (int nf = 0; nf < 4; nf++) {
                    MMA_S8(acc1[mf][nf], aa[mf], ba[nf]);
                    MMA_S8(acc2[mf][nf], aa[mf], bb[nf]);
                    MMA_S8(acc2[mf][nf], ab[mf], ba[nf]);
                }
        }
        __syncthreads();
    }

    const float INV252 = 1.f / 252.f;
    #pragma unroll
    for (int mf = 0; mf < 2; mf++) {
        #pragma unroll
        for (int nf = 0; nf < 4; nf++) {
            int rbase = m0 + warpM * 32 + mf * 16 + (lane >> 2);
            int e = e0 + warpN * 32 + nf * 8 + (lane & 3) * 2;
            float swx = op.Ws[e], swy = op.Ws[e + 1];
            #pragma unroll
            for (int half = 0; half < 2; half++) {
                int m = rbase + half * 8;
                float sx = As[m] * op.scale;
                float vx = sx * swx * ((float)acc1[mf][nf][half*2+0] + (float)acc2[mf][nf][half*2+0] * INV252);
                float vy = sx * swy * ((float)acc1[mf][nf][half*2+1] + (float)acc2[mf][nf][half*2+1] * INV252);
                if (Lhead > 0) {
                    int bI = m / Lhead, l = m - bI * Lhead;
                    size_t idx = ((((size_t)bI * NH + (e >> 6)) * (size_t)Lhead + l) << 6) + (e & 63);
                    __nv_bfloat162 hi = __floats2bfloat162_rn(vx, vy);
                    float lx = vx - __bfloat162float(__low2bfloat16(hi));
                    float ly = vy - __bfloat162float(__high2bfloat16(hi));
                    *(__nv_bfloat162*)&op.Ch[idx] = hi;
                    *(__nv_bfloat162*)&op.Cl[idx] = __floats2bfloat162_rn(lx, ly);
                } else {
                    float2 v; v.x = vx; v.y = vy;
                    *(float2*)&op.Cf[(size_t)m * DM + e] = v;
                }
            }
        }
    }
}

// ---------------- flash attention (HMMA; 2 CTAs/SM) ----------------
#define QROW     144
#define AQH_OFF  0
#define AQL_OFF  18432
#define AKV_OFF  36864
#define AKV_ARR  9216
#define AKV_BUF  36864
#define AMSK_OFF 110592
#define ASMEM    111104

__global__ __launch_bounds__(256, 2) void fattn(
    const bf16* __restrict__ Qh, const bf16* __restrict__ Ql,
    const bf16* __restrict__ KGh, const bf16* __restrict__ KGl,
    const bf16* __restrict__ VGh, const bf16* __restrict__ VGl,
    const bf16* __restrict__ KTh, const bf16* __restrict__ KTl,
    const bf16* __restrict__ VTh, const bf16* __restrict__ VTl,
    const float* __restrict__ mask,
    float* __restrict__ outF,
    float* __restrict__ pO, float* __restrict__ pML,
    int NB, int QL, int X, int nsplit)
{
    extern __shared__ __align__(128) char smem[];
    const uint32_t sbase = smem_to_u32(smem);
    const int tid  = threadIdx.x;
    const int wid  = tid >> 5;
    const int lane = tid & 31;
    const int bh = blockIdx.x / NB;
    const int n  = blockIdx.x - bh * NB;
    const int b  = bh >> 4, h = bh & 15;
    const int LTOT = NB * QL;
    const int LO   = n * QL;
    const int T    = X >> 6;

    int split, qb;
    if (nsplit > 1) { split = blockIdx.y; qb = 0; }
    else            { split = 0;          qb = blockIdx.y; }
    const int tper = T / nsplit, trem = T - tper * nsplit;
    const int tile0  = split * tper + (split < trem ? split : trem);
    const int ntiles = tper + (split < trem ? 1 : 0);
    const int q0 = n * QL + qb * 128;

    const bf16* gk[4] = { KGh, KGl, VGh, VGl };
    const bf16* tk[4] = { KTh, KTl, VTh, VTl };

    auto issueKV = [&](int stg, int tile) {
        int xb = tile * 64;
        uint32_t sb = sbase + AKV_OFF + stg * AKV_BUF;
        #pragma unroll
        for (int i = 0; i < 8; i++) {
            int c = tid + i * 256;
            int arr = c >> 9, u = c & 511;
            int row = u >> 3, seg = u & 7;
            int x = xb + row;
            const bf16* src = (x < GG)
                ? gk[arr] + (((size_t)bh * GG + x) << 6) + seg * 8
                : tk[arr] + (((size_t)bh * SL + (x - GG + LO)) << 6) + seg * 8;
            CP_ASYNC16(sb + arr * AKV_ARR + row * QROW + seg * 16, src);
        }
        if (tid < 64) {
            int x = xb + tid;
            float mv = (x < GG) ? 0.f : mask[(size_t)b * SL + x - GG + LO];
            *(float*)(smem + AMSK_OFF + stg * 256 + tid * 4) = mv;
        }
    };

    #pragma unroll
    for (int i = 0; i < 8; i++) {
        int c = tid + i * 256;
        int arr = c >> 10, u = c & 1023;
        int row = u >> 3, seg = u & 7;
        const bf16* src = (arr ? Ql : Qh) + (((size_t)bh * LTOT + q0 + row) << 6) + seg * 8;
        CP_ASYNC16(sbase + (arr ? AQL_OFF : AQH_OFF) + row * QROW + seg * 16, src);
    }
    issueKV(0, tile0);
    CP_COMMIT();

    float o[8][4];
    #pragma unroll
    for (int i = 0; i < 8; i++)
        #pragma unroll
        for (int j = 0; j < 4; j++) o[i][j] = 0.f;
    float runA = -INFINITY, runB = -INFINITY, lA = 0.f, lB = 0.f;

    const int r = lane & 15, c8 = lane >> 4;
    const int rr = lane & 7, sub = lane >> 3;

    #pragma unroll 1
    for (int t = 0; t < ntiles; t++) {
        if (t + 1 < ntiles) {
            issueKV((t + 1) & 1, tile0 + t + 1);
            CP_COMMIT();
            CP_WAIT1();
        } else {
            CP_WAIT0();
        }
        __syncthreads();

        const uint32_t kvb = sbase + AKV_OFF + (t & 1) * AKV_BUF;
        const uint32_t sKh = kvb, sKl = kvb + AKV_ARR;
        const uint32_t sVh = kvb + 2 * AKV_ARR, sVl = kvb + 3 * AKV_ARR;
        const char* msk = smem + AMSK_OFF + (t & 1) * 256;

        float s[8][4];
        #pragma unroll
        for (int i = 0; i < 8; i++)
            #pragma unroll
            for (int j = 0; j < 4; j++) s[i][j] = 0.f;

        // QK: stream K fragments per nf2 group (reduced register pressure)
        #pragma unroll
        for (int ks = 0; ks < 4; ks++) {
            uint32_t qh4[4], ql4[4];
            uint32_t qoff = (uint32_t)(wid * 16 + r) * QROW + (uint32_t)(ks * 16 + c8 * 8) * 2;
            LDMX4(qh4[0], qh4[1], qh4[2], qh4[3], sbase + AQH_OFF + qoff);
            LDMX4(ql4[0], ql4[1], ql4[2], ql4[3], sbase + AQL_OFF + qoff);
            #pragma unroll
            for (int nf2 = 0; nf2 < 4; nf2++) {
                uint32_t boff = (uint32_t)(nf2 * 16 + ((sub >> 1) << 3) + rr) * QROW
                              + (uint32_t)(ks * 16 + ((sub & 1) << 3)) * 2;
                uint32_t kh[2][2], kl[2][2];
                LDMX4(kh[0][0], kh[0][1], kh[1][0], kh[1][1], sKh + boff);
                LDMX4(kl[0][0], kl[0][1], kl[1][0], kl[1][1], sKl + boff);
                #pragma unroll
                for (int j = 0; j < 2; j++) {
                    MMA_BF16(s[2*nf2+j], qh4, kh[j]);
                    MMA_BF16(s[2*nf2+j], qh4, kl[j]);
                    MMA_BF16(s[2*nf2+j], ql4, kh[j]);
                }
            }
        }

        #pragma unroll
        for (int nf = 0; nf < 8; nf++) {
            float2 mv = *(const float2*)(msk + (nf * 8 + (lane & 3) * 2) * 4);
            s[nf][0] += mv.x; s[nf][1] += mv.y;
            s[nf][2] += mv.x; s[nf][3] += mv.y;
        }
        float mA = -INFINITY, mB = -INFINITY;
        #pragma unroll
        for (int nf = 0; nf < 8; nf++) {
            mA = fmaxf(mA, fmaxf(s[nf][0], s[nf][1]));
            mB = fmaxf(mB, fmaxf(s[nf][2], s[nf][3]));
        }
        mA = fmaxf(mA, __shfl_xor_sync(0xffffffffu, mA, 1));
        mA = fmaxf(mA, __shfl_xor_sync(0xffffffffu, mA, 2));
        mB = fmaxf(mB, __shfl_xor_sync(0xffffffffu, mB, 1));
        mB = fmaxf(mB, __shfl_xor_sync(0xffffffffu, mB, 2));
        float nA = fmaxf(runA, mA), nB = fmaxf(runB, mB);
        float cA = __expf(runA - nA), cB = __expf(runB - nB);
        runA = nA; runB = nB;

        uint32_t phA[8], phB[8], plA[8], plB[8];
        float sumA = 0.f, sumB = 0.f;
        #pragma unroll
        for (int nf = 0; nf < 8; nf++) {
            float p0 = __expf(s[nf][0] - nA), p1 = __expf(s[nf][1] - nA);
            float p2 = __expf(s[nf][2] - nB), p3 = __expf(s[nf][3] - nB);
            sumA += p0 + p1; sumB += p2 + p3;
            __nv_bfloat162 h01 = __floats2bfloat162_rn(p0, p1);
            __nv_bfloat162 h23 = __floats2bfloat162_rn(p2, p3);
            phA[nf] = *reinterpret_cast<uint32_t*>(&h01);
            phB[nf] = *reinterpret_cast<uint32_t*>(&h23);
            plA[nf] = pack_bf16x2(p0 - __bfloat162float(__low2bfloat16(h01)),
                                  p1 - __bfloat162float(__high2bfloat16(h01)));
            plB[nf] = pack_bf16x2(p2 - __bfloat162float(__low2bfloat16(h23)),
                                  p3 - __bfloat162float(__high2bfloat16(h23)));
        }
        sumA += __shfl_xor_sync(0xffffffffu, sumA, 1);
        sumA += __shfl_xor_sync(0xffffffffu, sumA, 2);
        sumB += __shfl_xor_sync(0xffffffffu, sumB, 1);
        sumB += __shfl_xor_sync(0xffffffffu, sumB, 2);
        lA = lA * cA + sumA;
        lB = lB * cB + sumB;
        #pragma unroll
        for (int i = 0; i < 8; i++) {
            o[i][0] *= cA; o[i][1] *= cA; o[i][2] *= cB; o[i][3] *= cB;
        }

        #pragma unroll
        for (int ks = 0; ks < 4; ks++) {
            uint32_t aH[4] = { phA[2*ks], phB[2*ks], phA[2*ks+1], phB[2*ks+1] };
            uint32_t aL4[4] = { plA[2*ks], plB[2*ks], plA[2*ks+1], plB[2*ks+1] };
            #pragma unroll
            for (int jf2 = 0; jf2 < 4; jf2++) {
                uint32_t voff = (uint32_t)(ks * 16 + r) * QROW + (uint32_t)(jf2 * 16 + c8 * 8) * 2;
                uint32_t vh4[4], vl4[4];
                LDMT4(vh4[0], vh4[1], vh4[2], vh4[3], sVh + voff);
                LDMT4(vl4[0], vl4[1], vl4[2], vl4[3], sVl + voff);
                uint32_t b0h[2] = { vh4[0], vh4[1] }, b1h[2] = { vh4[2], vh4[3] };
                uint32_t b0l[2] = { vl4[0], vl4[1] }, b1l[2] = { vl4[2], vl4[3] };
                MMA_BF16(o[2*jf2],   aH,  b0h);
                MMA_BF16(o[2*jf2],   aH,  b0l);
                MMA_BF16(o[2*jf2],   aL4, b0h);
                MMA_BF16(o[2*jf2+1], aH,  b1h);
                MMA_BF16(o[2*jf2+1], aH,  b1l);
                MMA_BF16(o[2*jf2+1], aL4, b1h);
            }
        }
        __syncthreads();
    }

    if (pO) {
        int pb = (bh * nsplit + split) * GG;
        int qA = wid * 16 + (lane >> 2);
        int qB = qA + 8;
        #pragma unroll
        for (int nf = 0; nf < 8; nf++) {
            int f = nf * 8 + (lane & 3) * 2;
            float2 vA; vA.x = o[nf][0]; vA.y = o[nf][1];
            float2 vB; vB.x = o[nf][2]; vB.y = o[nf][3];
            *(float2*)&pO[((size_t)(pb + qA)) * FF + f] = vA;
            *(float2*)&pO[((size_t)(pb + qB)) * FF + f] = vB;
        }
        if ((lane & 3) == 0) {
            pML[(size_t)(pb + qA) * 2 + 0] = runA;
            pML[(size_t)(pb + qA) * 2 + 1] = lA;
            pML[(size_t)(pb + qB) * 2 + 0] = runB;
            pML[(size_t)(pb + qB) * 2 + 1] = lB;
        }
        return;
    }

    float iA = 1.f / lA, iB = 1.f / lB;
    int rowA = q0 + wid * 16 + (lane >> 2);
    size_t baseA = ((size_t)b * LTOT + rowA) * DM + h * 64;
    size_t baseB = baseA + (size_t)8 * DM;
    #pragma unroll
    for (int nf = 0; nf < 8; nf++) {
        int f = nf * 8 + (lane & 3) * 2;
        float2 vA; vA.x = o[nf][0] * iA; vA.y = o[nf][1] * iA;
        float2 vB; vB.x = o[nf][2] * iB; vB.y = o[nf][3] * iB;
        *(float2*)&outF[baseA + f] = vA;
        *(float2*)&outF[baseB + f] = vB;
    }
}

// ---------------- split-K reduction ----------------
__global__ __launch_bounds__(256) void reduce_splitk(
    const float* __restrict__ pO, const float* __restrict__ pML,
    float* __restrict__ outF)
{
    int w = (blockIdx.x * 256 + threadIdx.x) >> 5;
    int lane = threadIdx.x & 31;
    if (w >= BB * NH * GG) return;
    int bh = w >> 7, q = w & (GG - 1);
    int b = bh >> 4, h = bh & 15;

    float mstar = -INFINITY;
    #pragma unroll
    for (int s = 0; s < NSPLIT; s++)
        mstar = fmaxf(mstar, pML[(size_t)((bh * NSPLIT + s) * GG + q) * 2]);

    float L = 0.f, o0 = 0.f, o1 = 0.f;
    #pragma unroll
    for (int s = 0; s < NSPLIT; s++) {
        size_t ridx = (size_t)(bh * NSPLIT + s) * GG + q;
        float ms = pML[ridx * 2 + 0];
        float ls = pML[ridx * 2 + 1];
        float c = __expf(ms - mstar);
        L  += ls * c;
        o0 += pO[ridx * FF + lane]      * c;
        o1 += pO[ridx * FF + lane + 32] * c;
    }
    float inv = 1.f / L;
    size_t base = ((size_t)b * GG + q) * DM + h * 64;
    outF[base + lane]      = o0 * inv;
    outF[base + lane + 32] = o1 * inv;
}

// ---------------- host ----------------
extern "C" void kernel_launch(void* const* d_in, const int* in_sizes, int n_in,
                              void* d_out, int out_size)
{
    const float* tok  = (const float*)d_in[0];
    const float* glob = (const float*)d_in[1];
    const float* mask = (const float*)d_in[2];
    const float* Wq   = (const float*)d_in[3];
    const float* Wk   = (const float*)d_in[4];
    const float* Wv   = (const float*)d_in[5];
    const float* Wo   = (const float*)d_in[6];
    float* out = (float*)d_out;

    int8_t *tokA,*tokB,*globA,*globB,*wqA,*wqB,*wkA,*wkB,*wvA,*wvB,*woA,*woB,*aLA,*aLB,*aGA,*aGB;
    float *tokS,*globS,*wqS,*wkS,*wvS,*woS,*aLS,*aGS,*aLp,*aGp,*pO,*pML;
    cudaGetSymbolAddress((void**)&tokA, g_tokA);   cudaGetSymbolAddress((void**)&tokB, g_tokB);
    cudaGetSymbolAddress((void**)&tokS, g_tokS);
    cudaGetSymbolAddress((void**)&globA, g_globA); cudaGetSymbolAddress((void**)&globB, g_globB);
    cudaGetSymbolAddress((void**)&globS, g_globS);
    cudaGetSymbolAddress((void**)&wqA, g_wqA); cudaGetSymbolAddress((void**)&wqB, g_wqB);
    cudaGetSymbolAddress((void**)&wqS, g_wqS);
    cudaGetSymbolAddress((void**)&wkA, g_wkA); cudaGetSymbolAddress((void**)&wkB, g_wkB);
    cudaGetSymbolAddress((void**)&wkS, g_wkS);
    cudaGetSymbolAddress((void**)&wvA, g_wvA); cudaGetSymbolAddress((void**)&wvB, g_wvB);
    cudaGetSymbolAddress((void**)&wvS, g_wvS);
    cudaGetSymbolAddress((void**)&woA, g_woA); cudaGetSymbolAddress((void**)&woB, g_woB);
    cudaGetSymbolAddress((void**)&woS, g_woS);
    cudaGetSymbolAddress((void**)&aLA, g_aLA); cudaGetSymbolAddress((void**)&aLB, g_aLB);
    cudaGetSymbolAddress((void**)&aLS, g_aLS);
    cudaGetSymbolAddress((void**)&aGA, g_aGA); cudaGetSymbolAddress((void**)&aGB, g_aGB);
    cudaGetSymbolAddress((void**)&aGS, g_aGS);
    cudaGetSymbolAddress((void**)&aLp, g_aL);  cudaGetSymbolAddress((void**)&aGp, g_aG);
    cudaGetSymbolAddress((void**)&pO, g_pO);   cudaGetSymbolAddress((void**)&pML, g_pML);

    bf16 *qTh,*qTl,*kTh,*kTl,*vTh,*vTl,*qGh,*qGl,*kGh,*kGl,*vGh,*vGl;
    cudaGetSymbolAddress((void**)&qTh, g_qTh); cudaGetSymbolAddress((void**)&qTl, g_qTl);
    cudaGetSymbolAddress((void**)&kTh, g_kTh); cudaGetSymbolAddress((void**)&kTl, g_kTl);
    cudaGetSymbolAddress((void**)&vTh, g_vTh); cudaGetSymbolAddress((void**)&vTl, g_vTl);
    cudaGetSymbolAddress((void**)&qGh, g_qGh); cudaGetSymbolAddress((void**)&qGl, g_qGl);
    cudaGetSymbolAddress((void**)&kGh, g_kGh); cudaGetSymbolAddress((void**)&kGl, g_kGl);
    cudaGetSymbolAddress((void**)&vGh, g_vGh); cudaGetSymbolAddress((void**)&vGl, g_vGl);

    cudaFuncSetAttribute(gemm_s8, cudaFuncAttributeMaxDynamicSharedMemorySize, QSMEM);
    cudaFuncSetAttribute(fattn, cudaFuncAttributeMaxDynamicSharedMemorySize, ASMEM);

    const float scl = 0.125f;

    // ---- quantize all 6 fp32 inputs ----
    QJobs qin;
    qin.j[0] = { tok,  tokA,  tokB,  tokS,  BB*SL };
    qin.j[1] = { glob, globA, globB, globS, BB*GG };
    qin.j[2] = { Wq, wqA, wqB, wqS, DM };
    qin.j[3] = { Wk, wkA, wkB, wkS, DM };
    qin.j[4] = { Wv, wvA, wvB, wvS, DM };
    qin.j[5] = { Wo, woA, woB, woS, DM };
    quant_rows<<<dim3(BB*SL, 6), 256>>>(qin);

    GemmOpQ opQ  = {wqA, wqB, wqS, qTh, qTl, 0, scl};
    GemmOpQ opK  = {wkA, wkB, wkS, kTh, kTl, 0, 1.f};
    GemmOpQ opV  = {wvA, wvB, wvS, vTh, vTl, 0, 1.f};
    GemmOpQ opQg = {wqA, wqB, wqS, qGh, qGl, 0, scl};
    GemmOpQ opKg = {wkA, wkB, wkS, kGh, kGl, 0, 1.f};
    GemmOpQ opVg = {wvA, wvB, wvS, vGh, vGl, 0, 1.f};

    // ---- projections -> split bf16 head-split ----
    dim3 gTok(DM/64, (BB*SL)/128, 3);
    dim3 gGlb(DM/64, (BB*GG)/128, 3);
    gemm_s8<<<gTok, 256, QSMEM>>>(tokA,  tokB,  tokS,  opQ,  opK,  opV,  SL);
    gemm_s8<<<gGlb, 256, QSMEM>>>(globA, globB, globS, opQg, opKg, opVg, GG);

    // ---- local flash attention (fp32 out) ----
    dim3 gridL(BB*NH*NBL, KBL/128);
    fattn<<<gridL, 256, ASMEM>>>(qTh, qTl, kGh, kGl, vGh, vGl,
                                 kTh, kTl, vTh, vTl, mask, aLp,
                                 0, 0, NBL, KBL, GG + KBL, 1);

    // ---- global flash attention: split-K ----
    dim3 gridGA(BB*NH, NSPLIT);
    fattn<<<gridGA, 256, ASMEM>>>(qGh, qGl, kGh, kGl, vGh, vGl,
                                  kTh, kTl, vTh, vTl, mask, 0,
                                  pO, pML, 1, GG, GG + SL, NSPLIT);
    int nRows = BB * NH * GG;
    reduce_splitk<<<(nRows * 32 + 255) / 256, 256>>>(pO, pML, aGp);

    // ---- quantize attention outputs ----
    QJobs qat;
    qat.j[0] = { aLp, aLA, aLB, aLS, BB*SL };
    qat.j[1] = { aGp, aGA, aGB, aGS, BB*GG };
    qat.j[2] = { aGp, aGA, aGB, aGS, 0 };
    qat.j[3] = { aGp, aGA, aGB, aGS, 0 };
    qat.j[4] = { aGp, aGA, aGB, aGS, 0 };
    qat.j[5] = { aGp, aGA, aGB, aGS, 0 };
    quant_rows<<<dim3(BB*SL, 2), 256>>>(qat);

    // ---- output projections (fp32 into d_out) ----
    GemmOpQ opOL = {woA, woB, woS, 0, 0, out, 1.f};
    GemmOpQ opOG = {woA, woB, woS, 0, 0, out + (size_t)BB*SL*DM, 1.f};
    dim3 gOL(DM/64, (BB*SL)/128, 1);
    dim3 gOG(DM/64, (BB*GG)/128, 1);
    gemm_s8<<<gOL, 256, QSMEM>>>(aLA, aLB, aLS, opOL, opOL, opOL, 0);
    gemm_s8<<<gOG, 256, QSMEM>>>(aGA, aGB, aGS, opOG, opOG, opOG, 0);
}

// round 17
// speedup vs baseline: 2.0298x; 1.0276x over previous
#include <cuda_runtime.h>
#include <cuda_bf16.h>
#include <math.h>
#include <stdint.h>

// ---------------- problem constants ----------------
#define BB   2      // batch
#define SL   4096   // token seq len
#define GG   128    // global tokens
#define DM   1024   // embed dim
#define NH   16     // heads
#define FF   64     // head dim
#define NBL  8      // local blocks per seq
#define KBL  512    // block size
#define NSPLIT 4    // split-K factor for global attention
#define GCTAS (BB*NH*NSPLIT)         // 128 global CTAs (scheduled first)
#define LCTAS (BB*NH*NBL*(KBL/128))  // 1024 local CTAs

typedef __nv_bfloat16 bf16;

// ---------------- scratch (static device, no allocation) ----------------
__device__ int8_t g_tokA[(size_t)BB*SL*DM],  g_tokB[(size_t)BB*SL*DM];
__device__ float  g_tokS[(size_t)BB*SL];
__device__ int8_t g_globA[(size_t)BB*GG*DM], g_globB[(size_t)BB*GG*DM];
__device__ float  g_globS[(size_t)BB*GG];
__device__ int8_t g_wqA[(size_t)DM*DM], g_wqB[(size_t)DM*DM];
__device__ float  g_wqS[DM];
__device__ int8_t g_wkA[(size_t)DM*DM], g_wkB[(size_t)DM*DM];
__device__ float  g_wkS[DM];
__device__ int8_t g_wvA[(size_t)DM*DM], g_wvB[(size_t)DM*DM];
__device__ float  g_wvS[DM];
__device__ int8_t g_woA[(size_t)DM*DM], g_woB[(size_t)DM*DM];
__device__ float  g_woS[DM];
__device__ int8_t g_aLA[(size_t)BB*SL*DM], g_aLB[(size_t)BB*SL*DM];
__device__ float  g_aLS[(size_t)BB*SL];
__device__ int8_t g_aGA[(size_t)BB*GG*DM], g_aGB[(size_t)BB*GG*DM];
__device__ float  g_aGS[(size_t)BB*GG];

__device__ float g_aL[(size_t)BB*SL*DM];
__device__ float g_aG[(size_t)BB*GG*DM];

__device__ bf16 g_qTh[(size_t)BB*NH*SL*FF], g_qTl[(size_t)BB*NH*SL*FF];
__device__ bf16 g_kTh[(size_t)BB*NH*SL*FF], g_kTl[(size_t)BB*NH*SL*FF];
__device__ bf16 g_vTh[(size_t)BB*NH*SL*FF], g_vTl[(size_t)BB*NH*SL*FF];
__device__ bf16 g_qGh[(size_t)BB*NH*GG*FF], g_qGl[(size_t)BB*NH*GG*FF];
__device__ bf16 g_kGh[(size_t)BB*NH*GG*FF], g_kGl[(size_t)BB*NH*GG*FF];
__device__ bf16 g_vGh[(size_t)BB*NH*GG*FF], g_vGl[(size_t)BB*NH*GG*FF];

__device__ float g_pO[(size_t)BB*NH*NSPLIT*GG*FF];
__device__ float g_pML[(size_t)BB*NH*NSPLIT*GG*2];

// ---------------- helpers (base-target ISA only) ----------------
__device__ __forceinline__ uint32_t smem_to_u32(const void* p) {
    uint32_t a;
    asm("{ .reg .u64 t; cvta.to.shared.u64 t, %1; cvt.u32.u64 %0, t; }" : "=r"(a) : "l"(p));
    return a;
}
#define CP_ASYNC16(saddr, gptr) \
    asm volatile("cp.async.cg.shared.global [%0], [%1], 16;" :: "r"(saddr), "l"(gptr))
#define CP_COMMIT() asm volatile("cp.async.commit_group;" ::: "memory")
#define CP_WAIT1()  asm volatile("cp.async.wait_group 1;" ::: "memory")
#define CP_WAIT0()  asm volatile("cp.async.wait_group 0;" ::: "memory")

#define LDMX4(d0, d1, d2, d3, addr) \
    asm volatile("ldmatrix.sync.aligned.m8n8.x4.shared.b16 {%0,%1,%2,%3}, [%4];" \
        : "=r"(d0), "=r"(d1), "=r"(d2), "=r"(d3) : "r"(addr))
#define LDMT4(d0, d1, d2, d3, addr) \
    asm volatile("ldmatrix.sync.aligned.m8n8.x4.trans.shared.b16 {%0,%1,%2,%3}, [%4];" \
        : "=r"(d0), "=r"(d1), "=r"(d2), "=r"(d3) : "r"(addr))

#define MMA_BF16(c, a, b) \
    asm volatile("mma.sync.aligned.m16n8k16.row.col.f32.bf16.bf16.f32 " \
        "{%0,%1,%2,%3}, {%4,%5,%6,%7}, {%8,%9}, {%0,%1,%2,%3};" \
        : "+f"((c)[0]), "+f"((c)[1]), "+f"((c)[2]), "+f"((c)[3]) \
        : "r"((a)[0]), "r"((a)[1]), "r"((a)[2]), "r"((a)[3]), \
          "r"((b)[0]), "r"((b)[1]))

#define MMA_S8(c, a, b) \
    asm volatile("mma.sync.aligned.m16n8k32.row.col.s32.s8.s8.s32 " \
        "{%0,%1,%2,%3}, {%4,%5,%6,%7}, {%8,%9}, {%0,%1,%2,%3};" \
        : "+r"((c)[0]), "+r"((c)[1]), "+r"((c)[2]), "+r"((c)[3]) \
        : "r"((a)[0]), "r"((a)[1]), "r"((a)[2]), "r"((a)[3]), \
          "r"((b)[0]), "r"((b)[1]))

__device__ __forceinline__ uint32_t pack_bf16x2(float x, float y) {
    __nv_bfloat162 t = __floats2bfloat162_rn(x, y);
    return *reinterpret_cast<uint32_t*>(&t);
}

// ---------------- per-row dual-level int8 quantization ----------------
struct QJob { const float* x; int8_t* qa; int8_t* qb; float* qs; int nrows; };
struct QJobs { QJob j[6]; };

__global__ __launch_bounds__(256) void quant_rows(QJobs jobs)
{
    QJob jb = jobs.j[blockIdx.y];
    int row = blockIdx.x;
    if (row >= jb.nrows) return;
    __shared__ float wmax[8];
    int tid = threadIdx.x;
    const float4 v = ((const float4*)(jb.x + (size_t)row * DM))[tid];
    float m = fmaxf(fmaxf(fabsf(v.x), fabsf(v.y)), fmaxf(fabsf(v.z), fabsf(v.w)));
    #pragma unroll
    for (int o = 16; o; o >>= 1) m = fmaxf(m, __shfl_xor_sync(0xffffffffu, m, o));
    if ((tid & 31) == 0) wmax[tid >> 5] = m;
    __syncthreads();
    if (tid < 8) {
        float t = wmax[tid];
        #pragma unroll
        for (int o = 4; o; o >>= 1) t = fmaxf(t, __shfl_xor_sync(0xffu, t, o));
        if (tid == 0) wmax[0] = t;
    }
    __syncthreads();
    float rowmax = fmaxf(wmax[0], 1e-20f);
    float s = rowmax * (1.f / 126.f);
    float inv = 126.f / rowmax;

    int a0 = __float2int_rn(v.x * inv), a1 = __float2int_rn(v.y * inv);
    int a2 = __float2int_rn(v.z * inv), a3 = __float2int_rn(v.w * inv);
    float f252 = 252.f * inv;
    int b0 = __float2int_rn((v.x - a0 * s) * f252);
    int b1 = __float2int_rn((v.y - a1 * s) * f252);
    int b2 = __float2int_rn((v.z - a2 * s) * f252);
    int b3 = __float2int_rn((v.w - a3 * s) * f252);

    char4 ca; ca.x = (char)a0; ca.y = (char)a1; ca.z = (char)a2; ca.w = (char)a3;
    char4 cb; cb.x = (char)b0; cb.y = (char)b1; cb.z = (char)b2; cb.w = (char)b3;
    ((char4*)(jb.qa + (size_t)row * DM))[tid] = ca;
    ((char4*)(jb.qb + (size_t)row * DM))[tid] = cb;
    if (tid == 0) jb.qs[row] = s;
}

// ---------------- int8 dual-level GEMM (R13 winner, unchanged) ----------------
struct GemmOpQ {
    const int8_t *Wa, *Wb;
    const float* Ws;
    bf16 *Ch, *Cl;
    float* Cf;
    float scale;
};

#define QROWB  80
#define ATILE  (128 * QROWB)
#define BTILE  (64 * QROWB)
#define QSTAGE (2 * ATILE + 2 * BTILE)
#define QSMEM  (2 * QSTAGE)

__global__ __launch_bounds__(256, 2) void gemm_s8(
    const int8_t* __restrict__ Aa, const int8_t* __restrict__ Ab,
    const float* __restrict__ As,
    GemmOpQ op0, GemmOpQ op1, GemmOpQ op2, int Lhead)
{
    extern __shared__ __align__(128) char smem[];
    const uint32_t sbase = smem_to_u32(smem);
    const int tid  = threadIdx.x;
    const int wid  = tid >> 5;
    const int lane = tid & 31;
    const int warpM = wid & 3, warpN = wid >> 2;
    const int m0 = blockIdx.y * 128;
    const int e0 = blockIdx.x * 64;

    GemmOpQ op = (blockIdx.z == 0) ? op0 : ((blockIdx.z == 1) ? op1 : op2);

    const int8_t* srcA[2] = { Aa + (size_t)m0 * DM, Ab + (size_t)m0 * DM };
    const int8_t* srcW[2] = { op.Wa + (size_t)e0 * DM, op.Wb + (size_t)e0 * DM };

    int acc1[2][4][4], acc2[2][4][4];
    #pragma unroll
    for (int i = 0; i < 2; i++)
        #pragma unroll
        for (int j = 0; j < 4; j++)
            #pragma unroll
            for (int k = 0; k < 4; k++) { acc1[i][j][k] = 0; acc2[i][j][k] = 0; }

    auto issue = [&](int stg, int k0) {
        uint32_t sb = sbase + stg * QSTAGE;
        #pragma unroll
        for (int i = 0; i < 6; i++) {
            int c = tid + i * 256;
            const int8_t* g;
            uint32_t dst;
            if (c < 1024) {
                int arr = c >> 9, u = c & 511;
                int row = u >> 2, seg = u & 3;
                g = srcA[arr] + (size_t)row * DM + k0 + seg * 16;
                dst = sb + arr * ATILE + row * QROWB + seg * 16;
            } else {
                int c2 = c - 1024;
                int arr = c2 >> 8, u = c2 & 255;
                int row = u >> 2, seg = u & 3;
                g = srcW[arr] + (size_t)row * DM + k0 + seg * 16;
                dst = sb + 2 * ATILE + arr * BTILE + row * QROWB + seg * 16;
            }
            CP_ASYNC16(dst, g);
        }
    };

    issue(0, 0);
    CP_COMMIT();

    const int r = lane & 15, c8 = lane >> 4;
    const int rr = lane & 7, sub = lane >> 3;

    #pragma unroll 1
    for (int it = 0; it < 16; it++) {
        if (it + 1 < 16) {
            issue((it + 1) & 1, (it + 1) * 64);
            CP_COMMIT();
            CP_WAIT1();
        } else {
            CP_WAIT0();
        }
        __syncthreads();

        const uint32_t sb  = sbase + (it & 1) * QSTAGE;
        const uint32_t sAa = sb;
        const uint32_t sAb = sb + ATILE;
        const uint32_t sWa = sb + 2 * ATILE;
        const uint32_t sWb = sb + 2 * ATILE + BTILE;

        #pragma unroll
        for (int ks = 0; ks < 2; ks++) {
            uint32_t aa[2][4], ab[2][4];
            #pragma unroll
            for (int mf = 0; mf < 2; mf++) {
                uint32_t off = (uint32_t)(warpM * 32 + mf * 16 + r) * QROWB
                             + (uint32_t)(ks * 32 + c8 * 16);
                LDMX4(aa[mf][0], aa[mf][1], aa[mf][2], aa[mf][3], sAa + off);
                LDMX4(ab[mf][0], ab[mf][1], ab[mf][2], ab[mf][3], sAb + off);
            }
            uint32_t ba[4][2], bb[4][2];
            #pragma unroll
            for (int nf2 = 0; nf2 < 2; nf2++) {
                int n  = warpN * 32 + nf2 * 16 + ((sub >> 1) << 3) + rr;
                uint32_t off = (uint32_t)n * QROWB + (uint32_t)(ks * 32 + (sub & 1) * 16);
                LDMX4(ba[2*nf2][0], ba[2*nf2][1], ba[2*nf2+1][0], ba[2*nf2+1][1], sWa + off);
                LDMX4(bb[2*nf2][0], bb[2*nf2][1], bb[2*nf2+1][0], bb[2*nf2+1][1], sWb + off);
            }
            #pragma unroll
            for (int mf = 0; mf < 2; mf++)
                #pragma unroll
                for (int nf = 0; nf < 4; nf++) {
                    MMA_S8(acc1[mf][nf], aa[mf], ba[nf]);
                    MMA_S8(acc2[mf][nf], aa[mf], bb[nf]);
                    MMA_S8(acc2[mf][nf], ab[mf], ba[nf]);
                }
        }
        __syncthreads();
    }

    const float INV252 = 1.f / 252.f;
    #pragma unroll
    for (int mf = 0; mf < 2; mf++) {
        #pragma unroll
        for (int nf = 0; nf < 4; nf++) {
            int rbase = m0 + warpM * 32 + mf * 16 + (lane >> 2);
            int e = e0 + warpN * 32 + nf * 8 + (lane & 3) * 2;
            float swx = op.Ws[e], swy = op.Ws[e + 1];
            #pragma unroll
            for (int half = 0; half < 2; half++) {
                int m = rbase + half * 8;
                float sx = As[m] * op.scale;
                float vx = sx * swx * ((float)acc1[mf][nf][half*2+0] + (float)acc2[mf][nf][half*2+0] * INV252);
                float vy = sx * swy * ((float)acc1[mf][nf][half*2+1] + (float)acc2[mf][nf][half*2+1] * INV252);
                if (Lhead > 0) {
                    int bI = m / Lhead, l = m - bI * Lhead;
                    size_t idx = ((((size_t)bI * NH + (e >> 6)) * (size_t)Lhead + l) << 6) + (e & 63);
                    __nv_bfloat162 hi = __floats2bfloat162_rn(vx, vy);
                    float lx = vx - __bfloat162float(__low2bfloat16(hi));
                    float ly = vy - __bfloat162float(__high2bfloat16(hi));
                    *(__nv_bfloat162*)&op.Ch[idx] = hi;
                    *(__nv_bfloat162*)&op.Cl[idx] = __floats2bfloat162_rn(lx, ly);
                } else {
                    float2 v; v.x = vx; v.y = vy;
                    *(float2*)&op.Cf[(size_t)m * DM + e] = v;
                }
            }
        }
    }
}

// ---------------- fused flash attention: global split-K CTAs first, then local ----------------
#define QROW     144
#define AQH_OFF  0
#define AQL_OFF  18432
#define AKV_OFF  36864
#define AKV_ARR  9216
#define AKV_BUF  36864
#define AMSK_OFF 110592
#define ASMEM    111104

__global__ __launch_bounds__(256, 2) void fattn(
    const bf16* __restrict__ QTh, const bf16* __restrict__ QTl,
    const bf16* __restrict__ QGh, const bf16* __restrict__ QGl,
    const bf16* __restrict__ KGh, const bf16* __restrict__ KGl,
    const bf16* __restrict__ VGh, const bf16* __restrict__ VGl,
    const bf16* __restrict__ KTh, const bf16* __restrict__ KTl,
    const bf16* __restrict__ VTh, const bf16* __restrict__ VTl,
    const float* __restrict__ mask,
    float* __restrict__ outF,
    float* __restrict__ pO, float* __restrict__ pML)
{
    extern __shared__ __align__(128) char smem[];
    const uint32_t sbase = smem_to_u32(smem);
    const int tid  = threadIdx.x;
    const int wid  = tid >> 5;
    const int lane = tid & 31;

    const int id = blockIdx.x;
    const bool isG = (id < GCTAS);
    int bh, n, qb, split, QL, X, nsplit, LTOT;
    const bf16 *Qh, *Ql;
    if (isG) {
        bh = id >> 2; split = id & 3; n = 0; qb = 0;
        QL = GG; X = GG + SL; nsplit = NSPLIT; LTOT = GG;
        Qh = QGh; Ql = QGl;
    } else {
        int id2 = id - GCTAS;
        int bx = id2 >> 2; qb = id2 & 3;
        bh = bx >> 3; n = bx & 7; split = 0;
        QL = KBL; X = GG + KBL; nsplit = 1; LTOT = SL;
        Qh = QTh; Ql = QTl;
    }
    const int b = bh >> 4, h = bh & 15;
    const int LO = n * QL;
    const int T  = X >> 6;
    const int tper = T / nsplit, trem = T - tper * nsplit;
    const int tile0  = split * tper + (split < trem ? split : trem);
    const int ntiles = tper + (split < trem ? 1 : 0);
    const int q0 = n * QL + qb * 128;

    const bf16* gk[4] = { KGh, KGl, VGh, VGl };
    const bf16* tk[4] = { KTh, KTl, VTh, VTl };

    auto issueKV = [&](int stg, int tile) {
        int xb = tile * 64;
        uint32_t sb = sbase + AKV_OFF + stg * AKV_BUF;
        #pragma unroll
        for (int i = 0; i < 8; i++) {
            int c = tid + i * 256;
            int arr = c >> 9, u = c & 511;
            int row = u >> 3, seg = u & 7;
            int x = xb + row;
            const bf16* src = (x < GG)
                ? gk[arr] + (((size_t)bh * GG + x) << 6) + seg * 8
                : tk[arr] + (((size_t)bh * SL + (x - GG + LO)) << 6) + seg * 8;
            CP_ASYNC16(sb + arr * AKV_ARR + row * QROW + seg * 16, src);
        }
        if (tid < 64) {
            int x = xb + tid;
            float mv = (x < GG) ? 0.f : mask[(size_t)b * SL + x - GG + LO];
            *(float*)(smem + AMSK_OFF + stg * 256 + tid * 4) = mv;
        }
    };

    #pragma unroll
    for (int i = 0; i < 8; i++) {
        int c = tid + i * 256;
        int arr = c >> 10, u = c & 1023;
        int row = u >> 3, seg = u & 7;
        const bf16* src = (arr ? Ql : Qh) + (((size_t)bh * LTOT + q0 + row) << 6) + seg * 8;
        CP_ASYNC16(sbase + (arr ? AQL_OFF : AQH_OFF) + row * QROW + seg * 16, src);
    }
    issueKV(0, tile0);
    CP_COMMIT();

    float o[8][4];
    #pragma unroll
    for (int i = 0; i < 8; i++)
        #pragma unroll
        for (int j = 0; j < 4; j++) o[i][j] = 0.f;
    float runA = -INFINITY, runB = -INFINITY, lA = 0.f, lB = 0.f;

    const int r = lane & 15, c8 = lane >> 4;
    const int rr = lane & 7, sub = lane >> 3;

    #pragma unroll 1
    for (int t = 0; t < ntiles; t++) {
        if (t + 1 < ntiles) {
            issueKV((t + 1) & 1, tile0 + t + 1);
            CP_COMMIT();
            CP_WAIT1();
        } else {
            CP_WAIT0();
        }
        __syncthreads();

        const uint32_t kvb = sbase + AKV_OFF + (t & 1) * AKV_BUF;
        const uint32_t sKh = kvb, sKl = kvb + AKV_ARR;
        const uint32_t sVh = kvb + 2 * AKV_ARR, sVl = kvb + 3 * AKV_ARR;
        const char* msk = smem + AMSK_OFF + (t & 1) * 256;

        float s[8][4];
        #pragma unroll
        for (int i = 0; i < 8; i++)
            #pragma unroll
            for (int j = 0; j < 4; j++) s[i][j] = 0.f;

        #pragma unroll
        for (int ks = 0; ks < 4; ks++) {
            uint32_t qh4[4], ql4[4];
            uint32_t qoff = (uint32_t)(wid * 16 + r) * QROW + (uint32_t)(ks * 16 + c8 * 8) * 2;
            LDMX4(qh4[0], qh4[1], qh4[2], qh4[3], sbase + AQH_OFF + qoff);
            LDMX4(ql4[0], ql4[1], ql4[2], ql4[3], sbase + AQL_OFF + qoff);
            #pragma unroll
            for (int nf2 = 0; nf2 < 4; nf2++) {
                uint32_t boff = (uint32_t)(nf2 * 16 + ((sub >> 1) << 3) + rr) * QROW
                              + (uint32_t)(ks * 16 + ((sub & 1) << 3)) * 2;
                uint32_t kh[2][2], kl[2][2];
                LDMX4(kh[0][0], kh[0][1], kh[1][0], kh[1][1], sKh + boff);
                LDMX4(kl[0][0], kl[0][1], kl[1][0], kl[1][1], sKl + boff);
                #pragma unroll
                for (int j = 0; j < 2; j++) {
                    MMA_BF16(s[2*nf2+j], qh4, kh[j]);
                    MMA_BF16(s[2*nf2+j], qh4, kl[j]);
                    MMA_BF16(s[2*nf2+j], ql4, kh[j]);
                }
            }
        }

        #pragma unroll
        for (int nf = 0; nf < 8; nf++) {
            float2 mv = *(const float2*)(msk + (nf * 8 + (lane & 3) * 2) * 4);
            s[nf][0] += mv.x; s[nf][1] += mv.y;
            s[nf][2] += mv.x; s[nf][3] += mv.y;
        }
        float mA = -INFINITY, mB = -INFINITY;
        #pragma unroll
        for (int nf = 0; nf < 8; nf++) {
            mA = fmaxf(mA, fmaxf(s[nf][0], s[nf][1]));
            mB = fmaxf(mB, fmaxf(s[nf][2], s[nf][3]));
        }
        mA = fmaxf(mA, __shfl_xor_sync(0xffffffffu, mA, 1));
        mA = fmaxf(mA, __shfl_xor_sync(0xffffffffu, mA, 2));
        mB = fmaxf(mB, __shfl_xor_sync(0xffffffffu, mB, 1));
        mB = fmaxf(mB, __shfl_xor_sync(0xffffffffu, mB, 2));
        float nA = fmaxf(runA, mA), nB = fmaxf(runB, mB);
        float cA = __expf(runA - nA), cB = __expf(runB - nB);
        runA = nA; runB = nB;

        uint32_t phA[8], phB[8], plA[8], plB[8];
        float sumA = 0.f, sumB = 0.f;
        #pragma unroll
        for (int nf = 0; nf < 8; nf++) {
            float p0 = __expf(s[nf][0] - nA), p1 = __expf(s[nf][1] - nA);
            float p2 = __expf(s[nf][2] - nB), p3 = __expf(s[nf][3] - nB);
            sumA += p0 + p1; sumB += p2 + p3;
            __nv_bfloat162 h01 = __floats2bfloat162_rn(p0, p1);
            __nv_bfloat162 h23 = __floats2bfloat162_rn(p2, p3);
            phA[nf] = *reinterpret_cast<uint32_t*>(&h01);
            phB[nf] = *reinterpret_cast<uint32_t*>(&h23);
            plA[nf] = pack_bf16x2(p0 - __bfloat162float(__low2bfloat16(h01)),
                                  p1 - __bfloat162float(__high2bfloat16(h01)));
            plB[nf] = pack_bf16x2(p2 - __bfloat162float(__low2bfloat16(h23)),
                                  p3 - __bfloat162float(__high2bfloat16(h23)));
        }
        sumA += __shfl_xor_sync(0xffffffffu, sumA, 1);
        sumA += __shfl_xor_sync(0xffffffffu, sumA, 2);
        sumB += __shfl_xor_sync(0xffffffffu, sumB, 1);
        sumB += __shfl_xor_sync(0xffffffffu, sumB, 2);
        lA = lA * cA + sumA;
        lB = lB * cB + sumB;
        #pragma unroll
        for (int i = 0; i < 8; i++) {
            o[i][0] *= cA; o[i][1] *= cA; o[i][2] *= cB; o[i][3] *= cB;
        }

        #pragma unroll
        for (int ks = 0; ks < 4; ks++) {
            uint32_t aH[4] = { phA[2*ks], phB[2*ks], phA[2*ks+1], phB[2*ks+1] };
            uint32_t aL4[4] = { plA[2*ks], plB[2*ks], plA[2*ks+1], plB[2*ks+1] };
            #pragma unroll
            for (int jf2 = 0; jf2 < 4; jf2++) {
                uint32_t voff = (uint32_t)(ks * 16 + r) * QROW + (uint32_t)(jf2 * 16 + c8 * 8) * 2;
                uint32_t vh4[4], vl4[4];
                LDMT4(vh4[0], vh4[1], vh4[2], vh4[3], sVh + voff);
                LDMT4(vl4[0], vl4[1], vl4[2], vl4[3], sVl + voff);
                uint32_t b0h[2] = { vh4[0], vh4[1] }, b1h[2] = { vh4[2], vh4[3] };
                uint32_t b0l[2] = { vl4[0], vl4[1] }, b1l[2] = { vl4[2], vl4[3] };
                MMA_BF16(o[2*jf2],   aH,  b0h);
                MMA_BF16(o[2*jf2],   aH,  b0l);
                MMA_BF16(o[2*jf2],   aL4, b0h);
                MMA_BF16(o[2*jf2+1], aH,  b1h);
                MMA_BF16(o[2*jf2+1], aH,  b1l);
                MMA_BF16(o[2*jf2+1], aL4, b1h);
            }
        }
        __syncthreads();
    }

    if (isG) {
        int pb = (bh * NSPLIT + split) * GG;
        int qA = wid * 16 + (lane >> 2);
        int qB = qA + 8;
        #pragma unroll
        for (int nf = 0; nf < 8; nf++) {
            int f = nf * 8 + (lane & 3) * 2;
            float2 vA; vA.x = o[nf][0]; vA.y = o[nf][1];
            float2 vB; vB.x = o[nf][2]; vB.y = o[nf][3];
            *(float2*)&pO[((size_t)(pb + qA)) * FF + f] = vA;
            *(float2*)&pO[((size_t)(pb + qB)) * FF + f] = vB;
        }
        if ((lane & 3) == 0) {
            pML[(size_t)(pb + qA) * 2 + 0] = runA;
            pML[(size_t)(pb + qA) * 2 + 1] = lA;
            pML[(size_t)(pb + qB) * 2 + 0] = runB;
            pML[(size_t)(pb + qB) * 2 + 1] = lB;
        }
        return;
    }

    float iA = 1.f / lA, iB = 1.f / lB;
    int rowA = q0 + wid * 16 + (lane >> 2);
    size_t baseA = ((size_t)b * SL + rowA) * DM + h * 64;
    size_t baseB = baseA + (size_t)8 * DM;
    #pragma unroll
    for (int nf = 0; nf < 8; nf++) {
        int f = nf * 8 + (lane & 3) * 2;
        float2 vA; vA.x = o[nf][0] * iA; vA.y = o[nf][1] * iA;
        float2 vB; vB.x = o[nf][2] * iB; vB.y = o[nf][3] * iB;
        *(float2*)&outF[baseA + f] = vA;
        *(float2*)&outF[baseB + f] = vB;
    }
}

// ---------------- split-K reduction ----------------
__global__ __launch_bounds__(256) void reduce_splitk(
    const float* __restrict__ pO, const float* __restrict__ pML,
    float* __restrict__ outF)
{
    int w = (blockIdx.x * 256 + threadIdx.x) >> 5;
    int lane = threadIdx.x & 31;
    if (w >= BB * NH * GG) return;
    int bh = w >> 7, q = w & (GG - 1);
    int b = bh >> 4, h = bh & 15;

    float mstar = -INFINITY;
    #pragma unroll
    for (int s = 0; s < NSPLIT; s++)
        mstar = fmaxf(mstar, pML[(size_t)((bh * NSPLIT + s) * GG + q) * 2]);

    float L = 0.f, o0 = 0.f, o1 = 0.f;
    #pragma unroll
    for (int s = 0; s < NSPLIT; s++) {
        size_t ridx = (size_t)(bh * NSPLIT + s) * GG + q;
        float ms = pML[ridx * 2 + 0];
        float ls = pML[ridx * 2 + 1];
        float c = __expf(ms - mstar);
        L  += ls * c;
        o0 += pO[ridx * FF + lane]      * c;
        o1 += pO[ridx * FF + lane + 32] * c;
    }
    float inv = 1.f / L;
    size_t base = ((size_t)b * GG + q) * DM + h * 64;
    outF[base + lane]      = o0 * inv;
    outF[base + lane + 32] = o1 * inv;
}

// ---------------- host ----------------
extern "C" void kernel_launch(void* const* d_in, const int* in_sizes, int n_in,
                              void* d_out, int out_size)
{
    const float* tok  = (const float*)d_in[0];
    const float* glob = (const float*)d_in[1];
    const float* mask = (const float*)d_in[2];
    const float* Wq   = (const float*)d_in[3];
    const float* Wk   = (const float*)d_in[4];
    const float* Wv   = (const float*)d_in[5];
    const float* Wo   = (const float*)d_in[6];
    float* out = (float*)d_out;

    int8_t *tokA,*tokB,*globA,*globB,*wqA,*wqB,*wkA,*wkB,*wvA,*wvB,*woA,*woB,*aLA,*aLB,*aGA,*aGB;
    float *tokS,*globS,*wqS,*wkS,*wvS,*woS,*aLS,*aGS,*aLp,*aGp,*pO,*pML;
    cudaGetSymbolAddress((void**)&tokA, g_tokA);   cudaGetSymbolAddress((void**)&tokB, g_tokB);
    cudaGetSymbolAddress((void**)&tokS, g_tokS);
    cudaGetSymbolAddress((void**)&globA, g_globA); cudaGetSymbolAddress((void**)&globB, g_globB);
    cudaGetSymbolAddress((void**)&globS, g_globS);
    cudaGetSymbolAddress((void**)&wqA, g_wqA); cudaGetSymbolAddress((void**)&wqB, g_wqB);
    cudaGetSymbolAddress((void**)&wqS, g_wqS);
    cudaGetSymbolAddress((void**)&wkA, g_wkA); cudaGetSymbolAddress((void**)&wkB, g_wkB);
    cudaGetSymbolAddress((void**)&wkS, g_wkS);
    cudaGetSymbolAddress((void**)&wvA, g_wvA); cudaGetSymbolAddress((void**)&wvB, g_wvB);
    cudaGetSymbolAddress((void**)&wvS, g_wvS);
    cudaGetSymbolAddress((void**)&woA, g_woA); cudaGetSymbolAddress((void**)&woB, g_woB);
    cudaGetSymbolAddress((void**)&woS, g_woS);
    cudaGetSymbolAddress((void**)&aLA, g_aLA); cudaGetSymbolAddress((void**)&aLB, g_aLB);
    cudaGetSymbolAddress((void**)&aLS, g_aLS);
    cudaGetSymbolAddress((void**)&aGA, g_aGA); cudaGetSymbolAddress((void**)&aGB, g_aGB);
    cudaGetSymbolAddress((void**)&aGS, g_aGS);
    cudaGetSymbolAddress((void**)&aLp, g_aL);  cudaGetSymbolAddress((void**)&aGp, g_aG);
    cudaGetSymbolAddress((void**)&pO, g_pO);   cudaGetSymbolAddress((void**)&pML, g_pML);

    bf16 *qTh,*qTl,*kTh,*kTl,*vTh,*vTl,*qGh,*qGl,*kGh,*kGl,*vGh,*vGl;
    cudaGetSymbolAddress((void**)&qTh, g_qTh); cudaGetSymbolAddress((void**)&qTl, g_qTl);
    cudaGetSymbolAddress((void**)&kTh, g_kTh); cudaGetSymbolAddress((void**)&kTl, g_kTl);
    cudaGetSymbolAddress((void**)&vTh, g_vTh); cudaGetSymbolAddress((void**)&vTl, g_vTl);
    cudaGetSymbolAddress((void**)&qGh, g_qGh); cudaGetSymbolAddress((void**)&qGl, g_qGl);
    cudaGetSymbolAddress((void**)&kGh, g_kGh); cudaGetSymbolAddress((void**)&kGl, g_kGl);
    cudaGetSymbolAddress((void**)&vGh, g_vGh); cudaGetSymbolAddress((void**)&vGl, g_vGl);

    cudaFuncSetAttribute(gemm_s8, cudaFuncAttributeMaxDynamicSharedMemorySize, QSMEM);
    cudaFuncSetAttribute(fattn, cudaFuncAttributeMaxDynamicSharedMemorySize, ASMEM);

    const float scl = 0.125f;

    // ---- quantize all 6 fp32 inputs ----
    QJobs qin;
    qin.j[0] = { tok,  tokA,  tokB,  tokS,  BB*SL };
    qin.j[1] = { glob, globA, globB, globS, BB*GG };
    qin.j[2] = { Wq, wqA, wqB, wqS, DM };
    qin.j[3] = { Wk, wkA, wkB, wkS, DM };
    qin.j[4] = { Wv, wvA, wvB, wvS, DM };
    qin.j[5] = { Wo, woA, woB, woS, DM };
    quant_rows<<<dim3(BB*SL, 6), 256>>>(qin);

    GemmOpQ opQ  = {wqA, wqB, wqS, qTh, qTl, 0, scl};
    GemmOpQ opK  = {wkA, wkB, wkS, kTh, kTl, 0, 1.f};
    GemmOpQ opV  = {wvA, wvB, wvS, vTh, vTl, 0, 1.f};
    GemmOpQ opQg = {wqA, wqB, wqS, qGh, qGl, 0, scl};
    GemmOpQ opKg = {wkA, wkB, wkS, kGh, kGl, 0, 1.f};
    GemmOpQ opVg = {wvA, wvB, wvS, vGh, vGl, 0, 1.f};

    // ---- projections -> split bf16 head-split ----
    dim3 gTok(DM/64, (BB*SL)/128, 3);
    dim3 gGlb(DM/64, (BB*GG)/128, 3);
    gemm_s8<<<gTok, 256, QSMEM>>>(tokA,  tokB,  tokS,  opQ,  opK,  opV,  SL);
    gemm_s8<<<gGlb, 256, QSMEM>>>(globA, globB, globS, opQg, opKg, opVg, GG);

    // ---- fused flash attention (global split-K CTAs first, then local) ----
    fattn<<<GCTAS + LCTAS, 256, ASMEM>>>(qTh, qTl, qGh, qGl,
                                         kGh, kGl, vGh, vGl,
                                         kTh, kTl, vTh, vTl,
                                         mask, aLp, pO, pML);

    // ---- combine split-K partials ----
    int nRows = BB * NH * GG;
    reduce_splitk<<<(nRows * 32 + 255) / 256, 256>>>(pO, pML, aGp);

    // ---- quantize attention outputs ----
    QJobs qat;
    qat.j[0] = { aLp, aLA, aLB, aLS, BB*SL };
    qat.j[1] = { aGp, aGA, aGB, aGS, BB*GG };
    qat.j[2] = { aGp, aGA, aGB, aGS, 0 };
    qat.j[3] = { aGp, aGA, aGB, aGS, 0 };
    qat.j[4] = { aGp, aGA, aGB, aGS, 0 };
    qat.j[5] = { aGp, aGA, aGB, aGS, 0 };
    quant_rows<<<dim3(BB*SL, 2), 256>>>(qat);

    // ---- output projections (fp32 into d_out) ----
    GemmOpQ opOL = {woA, woB, woS, 0, 0, out, 1.f};
    GemmOpQ opOG = {woA, woB, woS, 0, 0, out + (size_t)BB*SL*DM, 1.f};
    dim3 gOL(DM/64, (BB*SL)/128, 1);
    dim3 gOG(DM/64, (BB*GG)/128, 1);
    gemm_s8<<<gOL, 256, QSMEM>>>(aLA, aLB, aLS, opOL, opOL, opOL, 0);
    gemm_s8<<<gOG, 256, QSMEM>>>(aGA, aGB, aGS, opOG, opOG, opOG, 0);
}